// round 11
// baseline (speedup 1.0000x reference)
#include <cuda_runtime.h>
#include <cuda_fp16.h>
#include <math.h>
#include <stdint.h>

#define DIM 256
#define BATCH 4
#define SEQ 4096
#define M_TOTAL (BATCH * SEQ)

// fp16 hi/lo scratch (allocation-free rule: device globals)
__device__ __half g_xh[M_TOTAL * DIM];
__device__ __half g_xl[M_TOTAL * DIM];
__device__ __half g_wh[3 * DIM * DIM];
__device__ __half g_wl[3 * DIM * DIM];
__device__ __half g_qh[M_TOTAL * DIM];
__device__ __half g_kh[M_TOTAL * DIM];
__device__ __half g_vh[M_TOTAL * DIM];

// ---------------------------------------------------------------------------
// Kernel 0: split x and W into fp16 hi/lo.
// ---------------------------------------------------------------------------
__device__ __forceinline__ void split4(const float4 v, __half* hp, __half* lp) {
    __half h0 = __float2half_rn(v.x), h1 = __float2half_rn(v.y);
    __half h2 = __float2half_rn(v.z), h3 = __float2half_rn(v.w);
    *(half2*)(hp)     = __halves2half2(h0, h1);
    *(half2*)(hp + 2) = __halves2half2(h2, h3);
    *(half2*)(lp)     = __halves2half2(__float2half_rn(v.x - __half2float(h0)),
                                       __float2half_rn(v.y - __half2float(h1)));
    *(half2*)(lp + 2) = __halves2half2(__float2half_rn(v.z - __half2float(h2)),
                                       __float2half_rn(v.w - __half2float(h3)));
}

__global__ __launch_bounds__(256) void split_kernel(
    const float* __restrict__ x,
    const float* __restrict__ Wq, const float* __restrict__ Wk,
    const float* __restrict__ Wv)
{
    const int tid = blockIdx.x * blockDim.x + threadIdx.x;
    const int nt  = gridDim.x * blockDim.x;
    for (int i = tid; i < M_TOTAL * DIM / 4; i += nt)
        split4(((const float4*)x)[i], g_xh + i * 4, g_xl + i * 4);
    const float* Ws[3] = {Wq, Wk, Wv};
#pragma unroll
    for (int s = 0; s < 3; s++) {
        const float4* wp = (const float4*)Ws[s];
        for (int i = tid; i < DIM * DIM / 4; i += nt)
            split4(wp[i], g_wh + s * DIM * DIM + i * 4, g_wl + s * DIM * DIM + i * 4);
    }
}

// ---------------------------------------------------------------------------
// Warp-MMA helpers (plain PTX — valid on compute_103)
// ---------------------------------------------------------------------------
__device__ __forceinline__ uint32_t smem_u32(const void* p) {
    return (uint32_t)__cvta_generic_to_shared(p);
}
__device__ __forceinline__ void cp16(uint32_t dst, const void* src) {
    asm volatile("cp.async.cg.shared.global [%0], [%1], 16;\n" :: "r"(dst), "l"(src));
}
__device__ __forceinline__ void ldm4(uint32_t r[4], uint32_t addr) {
    asm volatile("ldmatrix.sync.aligned.m8n8.x4.shared.b16 {%0,%1,%2,%3}, [%4];"
                 : "=r"(r[0]), "=r"(r[1]), "=r"(r[2]), "=r"(r[3]) : "r"(addr));
}
__device__ __forceinline__ void ldm4t(uint32_t r[4], uint32_t addr) {
    asm volatile("ldmatrix.sync.aligned.m8n8.x4.trans.shared.b16 {%0,%1,%2,%3}, [%4];"
                 : "=r"(r[0]), "=r"(r[1]), "=r"(r[2]), "=r"(r[3]) : "r"(addr));
}
__device__ __forceinline__ void mma16(float c[4], const uint32_t a[4],
                                      uint32_t b0, uint32_t b1) {
    asm volatile(
        "mma.sync.aligned.m16n8k16.row.col.f32.f16.f16.f32 "
        "{%0,%1,%2,%3}, {%4,%5,%6,%7}, {%8,%9}, {%0,%1,%2,%3};"
        : "+f"(c[0]), "+f"(c[1]), "+f"(c[2]), "+f"(c[3])
        : "r"(a[0]), "r"(a[1]), "r"(a[2]), "r"(a[3]), "r"(b0), "r"(b1));
}

#define KPB 528     // 256-half row pitch in bytes (+16B pad)
#define PPB 144     // 64-half row pitch in bytes (+16B pad)

// ---------------------------------------------------------------------------
// Kernel 1: QKV projection via 3-term fp16 MMA (fp32-accurate).
//   y = Xh*Wh + Xh*Wl + Xl*Wh + bias   -> qh / kh / vh (fp16)
// ---------------------------------------------------------------------------
#define QSM_XH 0
#define QSM_XL (QSM_XH + 64 * KPB)
#define QSM_WH (QSM_XL + 64 * KPB)
#define QSM_WL (QSM_WH + 64 * KPB)
#define QSMEM_BYTES (QSM_WL + 64 * KPB)   // 135168

extern __shared__ char smem_raw[];

__global__ __launch_bounds__(256, 1) void qkv_mma_kernel(
    const float* __restrict__ bq, const float* __restrict__ bk,
    const float* __restrict__ bv)
{
    const int tid = threadIdx.x;
    const int w = tid >> 5, lane = tid & 31;
    const int g = lane >> 2, tg = lane & 3;
    const int wq = w & 3, wn = w >> 2;
    const int wsel = blockIdx.x >> 2;
    const int n0   = (blockIdx.x & 3) * 64;
    const int m0   = blockIdx.y * 64;
    const float* bias = (wsel == 0) ? bq : (wsel == 1) ? bk : bv;

    const uint32_t sXH = smem_u32(smem_raw + QSM_XH);
    const uint32_t sXL = smem_u32(smem_raw + QSM_XL);
    const uint32_t sWH = smem_u32(smem_raw + QSM_WH);
    const uint32_t sWL = smem_u32(smem_raw + QSM_WL);

    {
        const __half* wh = g_wh + (size_t)wsel * DIM * DIM + (size_t)n0 * DIM;
        const __half* wl = g_wl + (size_t)wsel * DIM * DIM + (size_t)n0 * DIM;
#pragma unroll
        for (int it = 0; it < 8; it++) {
            int idx = it * 256 + tid, row = idx >> 5, u = idx & 31;
            uint32_t so = (uint32_t)(row * KPB + u * 16);
            size_t   xo = (size_t)(m0 + row) * DIM + u * 8;
            size_t   wo = (size_t)row * DIM + u * 8;
            cp16(sXH + so, g_xh + xo);
            cp16(sXL + so, g_xl + xo);
            cp16(sWH + so, wh + wo);
            cp16(sWL + so, wl + wo);
        }
    }
    asm volatile("cp.async.commit_group;\n" ::: "memory");
    asm volatile("cp.async.wait_group 0;\n" ::: "memory");
    __syncthreads();

    const int mm = lane >> 3, rr = lane & 7;
    const uint32_t aXh = sXH + (16 * wq + ((mm & 1) << 3) + rr) * KPB + (mm >> 1) * 16;
    const uint32_t aXl = sXL + (16 * wq + ((mm & 1) << 3) + rr) * KPB + (mm >> 1) * 16;
    const uint32_t bWh = sWH + (32 * wn + ((mm >> 1) << 3) + rr) * KPB + (mm & 1) * 16;
    const uint32_t bWl = sWL + (32 * wn + ((mm >> 1) << 3) + rr) * KPB + (mm & 1) * 16;

    float c[4][4];
#pragma unroll
    for (int n = 0; n < 4; n++)
#pragma unroll
        for (int j = 0; j < 4; j++) c[n][j] = 0.f;

#pragma unroll 4
    for (int s = 0; s < 16; s++) {
        uint32_t xh[4], xl[4], h0[4], h1[4], l0[4], l1[4];
        ldm4(xh, aXh + s * 32);
        ldm4(xl, aXl + s * 32);
        ldm4(h0, bWh + s * 32);
        ldm4(h1, bWh + 16 * KPB + s * 32);
        ldm4(l0, bWl + s * 32);
        ldm4(l1, bWl + 16 * KPB + s * 32);
        mma16(c[0], xh, h0[0], h0[1]);
        mma16(c[1], xh, h0[2], h0[3]);
        mma16(c[2], xh, h1[0], h1[1]);
        mma16(c[3], xh, h1[2], h1[3]);
        mma16(c[0], xh, l0[0], l0[1]);
        mma16(c[1], xh, l0[2], l0[3]);
        mma16(c[2], xh, l1[0], l1[1]);
        mma16(c[3], xh, l1[2], l1[3]);
        mma16(c[0], xl, h0[0], h0[1]);
        mma16(c[1], xl, h0[2], h0[3]);
        mma16(c[2], xl, h1[0], h1[1]);
        mma16(c[3], xl, h1[2], h1[3]);
    }

    __half* dst = (wsel == 0) ? g_qh : (wsel == 1) ? g_kh : g_vh;
    const int colg = n0 + 32 * wn + 2 * tg;
#pragma unroll
    for (int n = 0; n < 4; n++) {
        int col = colg + 8 * n;
        float b0 = bias[col], b1 = bias[col + 1];
#pragma unroll
        for (int h = 0; h < 2; h++) {
            int row = m0 + 16 * wq + g + 8 * h;
            float y0 = c[n][2 * h] + b0, y1 = c[n][2 * h + 1] + b1;
            *(half2*)&dst[(size_t)row * DIM + col] =
                __halves2half2(__float2half_rn(y0), __float2half_rn(y1));
        }
    }
}

// ---------------------------------------------------------------------------
// Kernel 2: flash attention, fp16 m16n8k16, 16 warps (512 threads).
// CTA = (batch, 64 queries); 64-key tiles.
//   S phase : warp grid 4q x 4k, warp tile 16q x 16k (16 k16-steps).
//   PV phase: warp grid 4q x 4d, warp tile 16q x 64d (4 k16-steps),
//             accumulators 32 regs/thread -> 512-thread CTA fits 64K regs.
// 4 warps/SMSP so HMMA from one warp overlaps LDSM latency of another.
// ---------------------------------------------------------------------------
#define SM_QH 0
#define SM_KH (SM_QH + 64 * KPB)
#define SM_VH (SM_KH + 64 * KPB)
#define SM_PH (SM_VH + 64 * KPB)
#define SM_LS (SM_PH + 64 * PPB)
#define SMEM_BYTES (SM_LS + 4 * 64 * 4)   // 111616

__global__ __launch_bounds__(512, 1) void attn_mma_kernel(float* __restrict__ out)
{
    const int tid  = threadIdx.x;
    const int w    = tid >> 5;
    const int lane = tid & 31;
    const int g    = lane >> 2;
    const int tg   = lane & 3;
    const int wq   = w & 3;          // q strip (16 rows)
    const int wk   = w >> 2;         // S: 16-key strip ; PV: 64-d strip
    const int bb   = blockIdx.y;
    const int q0   = blockIdx.x * 64;
    const size_t qbase = ((size_t)bb * SEQ + q0) * DIM;

    const uint32_t sQH = smem_u32(smem_raw + SM_QH);
    const uint32_t sKH = smem_u32(smem_raw + SM_KH);
    const uint32_t sVH = smem_u32(smem_raw + SM_VH);
    const uint32_t sPH = smem_u32(smem_raw + SM_PH);
    __half* PhS = (__half*)(smem_raw + SM_PH);
    float*  Ls  = (float*)(smem_raw + SM_LS);

    const int mm = lane >> 3, rr = lane & 7;
    const uint32_t aQh = sQH + (16 * wq + ((mm & 1) << 3) + rr) * KPB + (mm >> 1) * 16;
    const uint32_t bKh = sKH + (16 * wk + ((mm >> 1) << 3) + rr) * KPB + (mm & 1) * 16;
    const uint32_t aPh = sPH + (16 * wq + ((mm & 1) << 3) + rr) * PPB + (mm >> 1) * 16;
    const uint32_t bV  = sVH + (((mm & 1) << 3) + rr) * KPB + 128 * wk + (mm >> 1) * 16;

    // ---- prologue: group0 = {Qh, Kh(0)}, group1 = {Vh(0)} ----
    {
        const __half* kh = g_kh + ((size_t)bb * SEQ) * DIM;
#pragma unroll
        for (int it = 0; it < 4; it++) {
            int idx = it * 512 + tid, row = idx >> 5, u = idx & 31;
            uint32_t so = (uint32_t)(row * KPB + u * 16);
            size_t   go = (size_t)row * DIM + u * 8;
            cp16(sQH + so, g_qh + qbase + go);
            cp16(sKH + so, kh + go);
        }
    }
    asm volatile("cp.async.commit_group;\n" ::: "memory");
    {
        const __half* vp = g_vh + ((size_t)bb * SEQ) * DIM;
#pragma unroll
        for (int it = 0; it < 4; it++) {
            int idx = it * 512 + tid, row = idx >> 5, u = idx & 31;
            cp16(sVH + (uint32_t)(row * KPB + u * 16), vp + (size_t)row * DIM + u * 8);
        }
    }
    asm volatile("cp.async.commit_group;\n" ::: "memory");

    float o[8][4];
#pragma unroll
    for (int n = 0; n < 8; n++)
#pragma unroll
        for (int j = 0; j < 4; j++) o[n][j] = 0.f;
    float lr0 = 0.f, lr1 = 0.f;

    const int T = SEQ / 64;
    const float SC = 0.0625f;

    for (int tI = 0; tI < T; tI++) {
        asm volatile("cp.async.wait_group 1;\n" ::: "memory");  // K(tI) ready
        __syncthreads();

        // ---- S = Qh @ Kh^T : warp tile 16q x 16k, 16 k-steps ----
        float sc[2][4];
#pragma unroll
        for (int n = 0; n < 2; n++)
#pragma unroll
            for (int j = 0; j < 4; j++) sc[n][j] = 0.f;

#pragma unroll 8
        for (int s = 0; s < 16; s++) {
            uint32_t qh[4], k0[4];
            ldm4(qh, aQh + s * 32);
            ldm4(k0, bKh + s * 32);
            mma16(sc[0], qh, k0[0], k0[1]);
            mma16(sc[1], qh, k0[2], k0[3]);
        }

        // ---- softmax: p = exp(s/16), fp16 store, row partial sums ----
        {
            const int rowA = 16 * wq + g;
            const int colb = 16 * wk + 2 * tg;
            float ra = 0.f, rb = 0.f;
#pragma unroll
            for (int n = 0; n < 2; n++) {
                float p0 = __expf(sc[n][0] * SC);
                float p1 = __expf(sc[n][1] * SC);
                float p2 = __expf(sc[n][2] * SC);
                float p3 = __expf(sc[n][3] * SC);
                ra += p0 + p1;  rb += p2 + p3;
                *(half2*)&PhS[rowA * 72 + colb + 8 * n] =
                    __halves2half2(__float2half_rn(p0), __float2half_rn(p1));
                *(half2*)&PhS[(rowA + 8) * 72 + colb + 8 * n] =
                    __halves2half2(__float2half_rn(p2), __float2half_rn(p3));
            }
            ra += __shfl_xor_sync(0xffffffffu, ra, 1);
            ra += __shfl_xor_sync(0xffffffffu, ra, 2);
            rb += __shfl_xor_sync(0xffffffffu, rb, 1);
            rb += __shfl_xor_sync(0xffffffffu, rb, 2);
            lr0 += ra;  lr1 += rb;
        }
        __syncthreads();   // P visible; K reads done

        // ---- prefetch Kh(tI+1) (overlaps PV) ----
        if (tI + 1 < T) {
            const __half* kh = g_kh + ((size_t)bb * SEQ + (size_t)(tI + 1) * 64) * DIM;
#pragma unroll
            for (int it = 0; it < 4; it++) {
                int idx = it * 512 + tid, row = idx >> 5, u = idx & 31;
                cp16(sKH + (uint32_t)(row * KPB + u * 16), kh + (size_t)row * DIM + u * 8);
            }
        }
        asm volatile("cp.async.commit_group;\n" ::: "memory");

        asm volatile("cp.async.wait_group 1;\n" ::: "memory");  // V(tI) ready
        __syncthreads();

        // ---- PV: O += Ph*V ; warp tile 16q x 64d, V via ldmatrix.trans ----
#pragma unroll
        for (int s = 0; s < 4; s++) {
            uint32_t ph[4];
            ldm4(ph, aPh + s * 32);
#pragma unroll
            for (int c = 0; c < 4; c++) {
                uint32_t v[4];
                ldm4t(v, bV + (uint32_t)(s * 16 * KPB + c * 32));
                mma16(o[2 * c],     ph, v[0], v[1]);
                mma16(o[2 * c + 1], ph, v[2], v[3]);
            }
        }
        __syncthreads();   // V reads done

        // ---- prefetch Vh(tI+1) (overlaps next S) ----
        if (tI + 1 < T) {
            const __half* vp = g_vh + ((size_t)bb * SEQ + (size_t)(tI + 1) * 64) * DIM;
#pragma unroll
            for (int it = 0; it < 4; it++) {
                int idx = it * 512 + tid, row = idx >> 5, u = idx & 31;
                cp16(sVH + (uint32_t)(row * KPB + u * 16), vp + (size_t)row * DIM + u * 8);
            }
        }
        asm volatile("cp.async.commit_group;\n" ::: "memory");
    }

    // ---- epilogue: combine l over 4 k-strips, normalize, store ----
    const int rowA = 16 * wq + g;
    if (tg == 0) {
        Ls[wk * 64 + rowA]     = lr0;
        Ls[wk * 64 + rowA + 8] = lr1;
    }
    __syncthreads();
    const float inv0 = 1.0f / (Ls[rowA] + Ls[64 + rowA] + Ls[128 + rowA] + Ls[192 + rowA]);
    const float inv1 = 1.0f / (Ls[rowA + 8] + Ls[64 + rowA + 8] +
                               Ls[128 + rowA + 8] + Ls[192 + rowA + 8]);

    const size_t rA = ((size_t)bb * SEQ + q0 + rowA) * DIM + 64 * wk + 2 * tg;
#pragma unroll
    for (int n = 0; n < 8; n++) {
        float2 vA = make_float2(o[n][0] * inv0, o[n][1] * inv0);
        float2 vB = make_float2(o[n][2] * inv1, o[n][3] * inv1);
        *(float2*)&out[rA + 8 * n]           = vA;
        *(float2*)&out[rA + 8 * DIM + 8 * n] = vB;
    }
}

// ---------------------------------------------------------------------------
extern "C" void kernel_launch(void* const* d_in, const int* in_sizes, int n_in,
                              void* d_out, int out_size)
{
    const float* x  = (const float*)d_in[0];
    const float* Wq = (const float*)d_in[1];
    const float* bq = (const float*)d_in[2];
    const float* Wk = (const float*)d_in[3];
    const float* bk = (const float*)d_in[4];
    const float* Wv = (const float*)d_in[5];
    const float* bv = (const float*)d_in[6];
    float* out = (float*)d_out;

    (void)in_sizes; (void)n_in; (void)out_size;

    split_kernel<<<2048, 256>>>(x, Wq, Wk, Wv);

    cudaFuncSetAttribute(qkv_mma_kernel,
                         cudaFuncAttributeMaxDynamicSharedMemorySize, QSMEM_BYTES);
    qkv_mma_kernel<<<dim3(12, 256), 256, QSMEM_BYTES>>>(bq, bk, bv);

    cudaFuncSetAttribute(attn_mma_kernel,
                         cudaFuncAttributeMaxDynamicSharedMemorySize, SMEM_BYTES);
    attn_mma_kernel<<<dim3(SEQ / 64, BATCH), 512, SMEM_BYTES>>>(out);
}

// round 12
// speedup vs baseline: 1.2007x; 1.2007x over previous
#include <cuda_runtime.h>
#include <cuda_fp16.h>
#include <math.h>
#include <stdint.h>

#define DIM 256
#define BATCH 4
#define SEQ 4096
#define M_TOTAL (BATCH * SEQ)

// fp16 hi/lo scratch (allocation-free rule: device globals)
__device__ __half g_xh[M_TOTAL * DIM];
__device__ __half g_xl[M_TOTAL * DIM];
__device__ __half g_wh[3 * DIM * DIM];
__device__ __half g_wl[3 * DIM * DIM];
__device__ __half g_qh[M_TOTAL * DIM];
__device__ __half g_kh[M_TOTAL * DIM];
__device__ __half g_vh[M_TOTAL * DIM];

// ---------------------------------------------------------------------------
// Kernel 0: split x and W into fp16 hi/lo.
// ---------------------------------------------------------------------------
__device__ __forceinline__ void split4(const float4 v, __half* hp, __half* lp) {
    __half h0 = __float2half_rn(v.x), h1 = __float2half_rn(v.y);
    __half h2 = __float2half_rn(v.z), h3 = __float2half_rn(v.w);
    *(half2*)(hp)     = __halves2half2(h0, h1);
    *(half2*)(hp + 2) = __halves2half2(h2, h3);
    *(half2*)(lp)     = __halves2half2(__float2half_rn(v.x - __half2float(h0)),
                                       __float2half_rn(v.y - __half2float(h1)));
    *(half2*)(lp + 2) = __halves2half2(__float2half_rn(v.z - __half2float(h2)),
                                       __float2half_rn(v.w - __half2float(h3)));
}

__global__ __launch_bounds__(256) void split_kernel(
    const float* __restrict__ x,
    const float* __restrict__ Wq, const float* __restrict__ Wk,
    const float* __restrict__ Wv)
{
    const int tid = blockIdx.x * blockDim.x + threadIdx.x;
    const int nt  = gridDim.x * blockDim.x;
    for (int i = tid; i < M_TOTAL * DIM / 4; i += nt)
        split4(((const float4*)x)[i], g_xh + i * 4, g_xl + i * 4);
    const float* Ws[3] = {Wq, Wk, Wv};
#pragma unroll
    for (int s = 0; s < 3; s++) {
        const float4* wp = (const float4*)Ws[s];
        for (int i = tid; i < DIM * DIM / 4; i += nt)
            split4(wp[i], g_wh + s * DIM * DIM + i * 4, g_wl + s * DIM * DIM + i * 4);
    }
}

// ---------------------------------------------------------------------------
// Warp-MMA helpers (plain PTX — valid on compute_103)
// ---------------------------------------------------------------------------
__device__ __forceinline__ uint32_t smem_u32(const void* p) {
    return (uint32_t)__cvta_generic_to_shared(p);
}
__device__ __forceinline__ void cp16(uint32_t dst, const void* src) {
    asm volatile("cp.async.cg.shared.global [%0], [%1], 16;\n" :: "r"(dst), "l"(src));
}
__device__ __forceinline__ void ldm4(uint32_t r[4], uint32_t addr) {
    asm volatile("ldmatrix.sync.aligned.m8n8.x4.shared.b16 {%0,%1,%2,%3}, [%4];"
                 : "=r"(r[0]), "=r"(r[1]), "=r"(r[2]), "=r"(r[3]) : "r"(addr));
}
__device__ __forceinline__ void ldm4t(uint32_t r[4], uint32_t addr) {
    asm volatile("ldmatrix.sync.aligned.m8n8.x4.trans.shared.b16 {%0,%1,%2,%3}, [%4];"
                 : "=r"(r[0]), "=r"(r[1]), "=r"(r[2]), "=r"(r[3]) : "r"(addr));
}
__device__ __forceinline__ void mma16(float c[4], const uint32_t a[4],
                                      uint32_t b0, uint32_t b1) {
    asm volatile(
        "mma.sync.aligned.m16n8k16.row.col.f32.f16.f16.f32 "
        "{%0,%1,%2,%3}, {%4,%5,%6,%7}, {%8,%9}, {%0,%1,%2,%3};"
        : "+f"(c[0]), "+f"(c[1]), "+f"(c[2]), "+f"(c[3])
        : "r"(a[0]), "r"(a[1]), "r"(a[2]), "r"(a[3]), "r"(b0), "r"(b1));
}

#define KPB 528     // 256-half row pitch in bytes (+16B pad)
#define PPB 144     // 64-half row pitch in bytes (+16B pad)

// ---------------------------------------------------------------------------
// Kernel 1: QKV projection via 3-term fp16 MMA (fp32-accurate).
//   y = Xh*Wh + Xh*Wl + Xl*Wh + bias   -> qh / kh / vh (fp16)
// ---------------------------------------------------------------------------
#define QSM_XH 0
#define QSM_XL (QSM_XH + 64 * KPB)
#define QSM_WH (QSM_XL + 64 * KPB)
#define QSM_WL (QSM_WH + 64 * KPB)
#define QSMEM_BYTES (QSM_WL + 64 * KPB)   // 135168

extern __shared__ char smem_raw[];

__global__ __launch_bounds__(256, 1) void qkv_mma_kernel(
    const float* __restrict__ bq, const float* __restrict__ bk,
    const float* __restrict__ bv)
{
    const int tid = threadIdx.x;
    const int w = tid >> 5, lane = tid & 31;
    const int g = lane >> 2, tg = lane & 3;
    const int wq = w & 3, wn = w >> 2;
    const int wsel = blockIdx.x >> 2;
    const int n0   = (blockIdx.x & 3) * 64;
    const int m0   = blockIdx.y * 64;
    const float* bias = (wsel == 0) ? bq : (wsel == 1) ? bk : bv;

    const uint32_t sXH = smem_u32(smem_raw + QSM_XH);
    const uint32_t sXL = smem_u32(smem_raw + QSM_XL);
    const uint32_t sWH = smem_u32(smem_raw + QSM_WH);
    const uint32_t sWL = smem_u32(smem_raw + QSM_WL);

    {
        const __half* wh = g_wh + (size_t)wsel * DIM * DIM + (size_t)n0 * DIM;
        const __half* wl = g_wl + (size_t)wsel * DIM * DIM + (size_t)n0 * DIM;
#pragma unroll
        for (int it = 0; it < 8; it++) {
            int idx = it * 256 + tid, row = idx >> 5, u = idx & 31;
            uint32_t so = (uint32_t)(row * KPB + u * 16);
            size_t   xo = (size_t)(m0 + row) * DIM + u * 8;
            size_t   wo = (size_t)row * DIM + u * 8;
            cp16(sXH + so, g_xh + xo);
            cp16(sXL + so, g_xl + xo);
            cp16(sWH + so, wh + wo);
            cp16(sWL + so, wl + wo);
        }
    }
    asm volatile("cp.async.commit_group;\n" ::: "memory");
    asm volatile("cp.async.wait_group 0;\n" ::: "memory");
    __syncthreads();

    const int mm = lane >> 3, rr = lane & 7;
    const uint32_t aXh = sXH + (16 * wq + ((mm & 1) << 3) + rr) * KPB + (mm >> 1) * 16;
    const uint32_t aXl = sXL + (16 * wq + ((mm & 1) << 3) + rr) * KPB + (mm >> 1) * 16;
    const uint32_t bWh = sWH + (32 * wn + ((mm >> 1) << 3) + rr) * KPB + (mm & 1) * 16;
    const uint32_t bWl = sWL + (32 * wn + ((mm >> 1) << 3) + rr) * KPB + (mm & 1) * 16;

    float c[4][4];
#pragma unroll
    for (int n = 0; n < 4; n++)
#pragma unroll
        for (int j = 0; j < 4; j++) c[n][j] = 0.f;

#pragma unroll 4
    for (int s = 0; s < 16; s++) {
        uint32_t xh[4], xl[4], h0[4], h1[4], l0[4], l1[4];
        ldm4(xh, aXh + s * 32);
        ldm4(xl, aXl + s * 32);
        ldm4(h0, bWh + s * 32);
        ldm4(h1, bWh + 16 * KPB + s * 32);
        ldm4(l0, bWl + s * 32);
        ldm4(l1, bWl + 16 * KPB + s * 32);
        mma16(c[0], xh, h0[0], h0[1]);
        mma16(c[1], xh, h0[2], h0[3]);
        mma16(c[2], xh, h1[0], h1[1]);
        mma16(c[3], xh, h1[2], h1[3]);
        mma16(c[0], xh, l0[0], l0[1]);
        mma16(c[1], xh, l0[2], l0[3]);
        mma16(c[2], xh, l1[0], l1[1]);
        mma16(c[3], xh, l1[2], l1[3]);
        mma16(c[0], xl, h0[0], h0[1]);
        mma16(c[1], xl, h0[2], h0[3]);
        mma16(c[2], xl, h1[0], h1[1]);
        mma16(c[3], xl, h1[2], h1[3]);
    }

    __half* dst = (wsel == 0) ? g_qh : (wsel == 1) ? g_kh : g_vh;
    const int colg = n0 + 32 * wn + 2 * tg;
#pragma unroll
    for (int n = 0; n < 4; n++) {
        int col = colg + 8 * n;
        float b0 = bias[col], b1 = bias[col + 1];
#pragma unroll
        for (int h = 0; h < 2; h++) {
            int row = m0 + 16 * wq + g + 8 * h;
            float y0 = c[n][2 * h] + b0, y1 = c[n][2 * h + 1] + b1;
            *(half2*)&dst[(size_t)row * DIM + col] =
                __halves2half2(__float2half_rn(y0), __float2half_rn(y1));
        }
    }
}

// ---------------------------------------------------------------------------
// Kernel 2: flash attention, fp16 m16n8k16, 8 warps (R10 shape) +
//   (a) Q A-fragments register-resident across all 64 key tiles
//   (b) double-buffered K / V fragment pipelines (ldm s+1 before mma s)
// CTA = (batch, 64 queries); 64-key tiles.
//   S phase : warp grid 4q x 2k, warp tile 16q x 32k.
//   PV phase: warp grid 4q x 2d, warp tile 16q x 128d.
// ---------------------------------------------------------------------------
#define SM_QH 0
#define SM_KH (SM_QH + 64 * KPB)
#define SM_VH (SM_KH + 64 * KPB)
#define SM_PH (SM_VH + 64 * KPB)
#define SM_LS (SM_PH + 64 * PPB)
#define SMEM_BYTES (SM_LS + 2 * 64 * 4)   // 111104

__global__ __launch_bounds__(256, 1) void attn_mma_kernel(float* __restrict__ out)
{
    const int tid  = threadIdx.x;
    const int w    = tid >> 5;
    const int lane = tid & 31;
    const int g    = lane >> 2;
    const int tg   = lane & 3;
    const int wq   = w & 3;          // q strip (16 rows)
    const int wk   = w >> 2;         // S: 32-key strip ; PV: 128-d half
    const int bb   = blockIdx.y;
    const int q0   = blockIdx.x * 64;
    const size_t qbase = ((size_t)bb * SEQ + q0) * DIM;

    const uint32_t sQH = smem_u32(smem_raw + SM_QH);
    const uint32_t sKH = smem_u32(smem_raw + SM_KH);
    const uint32_t sVH = smem_u32(smem_raw + SM_VH);
    const uint32_t sPH = smem_u32(smem_raw + SM_PH);
    __half* PhS = (__half*)(smem_raw + SM_PH);
    float*  Ls  = (float*)(smem_raw + SM_LS);

    const int mm = lane >> 3, rr = lane & 7;
    const uint32_t aQh = sQH + (16 * wq + ((mm & 1) << 3) + rr) * KPB + (mm >> 1) * 16;
    const uint32_t bKh = sKH + (32 * wk + ((mm >> 1) << 3) + rr) * KPB + (mm & 1) * 16;
    const uint32_t aPh = sPH + (16 * wq + ((mm & 1) << 3) + rr) * PPB + (mm >> 1) * 16;
    const uint32_t bV  = sVH + (((mm & 1) << 3) + rr) * KPB + 256 * wk + (mm >> 1) * 16;

    // ---- prologue: group0 = {Qh, Kh(0)}, group1 = {Vh(0)} ----
    {
        const __half* kh = g_kh + ((size_t)bb * SEQ) * DIM;
#pragma unroll
        for (int it = 0; it < 8; it++) {
            int idx = it * 256 + tid, row = idx >> 5, u = idx & 31;
            uint32_t so = (uint32_t)(row * KPB + u * 16);
            size_t   go = (size_t)row * DIM + u * 8;
            cp16(sQH + so, g_qh + qbase + go);
            cp16(sKH + so, kh + go);
        }
    }
    asm volatile("cp.async.commit_group;\n" ::: "memory");
    {
        const __half* vp = g_vh + ((size_t)bb * SEQ) * DIM;
#pragma unroll
        for (int it = 0; it < 8; it++) {
            int idx = it * 256 + tid, row = idx >> 5, u = idx & 31;
            cp16(sVH + (uint32_t)(row * KPB + u * 16), vp + (size_t)row * DIM + u * 8);
        }
    }
    asm volatile("cp.async.commit_group;\n" ::: "memory");

    float o[16][4];
#pragma unroll
    for (int n = 0; n < 16; n++)
#pragma unroll
        for (int j = 0; j < 4; j++) o[n][j] = 0.f;
    float lr0 = 0.f, lr1 = 0.f;

    uint32_t qf[16][4];   // register-resident Q A-fragments (constant all tiles)

    const int T = SEQ / 64;
    const float SC = 0.0625f;

    for (int tI = 0; tI < T; tI++) {
        asm volatile("cp.async.wait_group 1;\n" ::: "memory");  // K(tI) (and Q) ready
        __syncthreads();

        if (tI == 0) {   // hoist Q fragments once
#pragma unroll
            for (int s = 0; s < 16; s++) ldm4(qf[s], aQh + s * 32);
        }

        // ---- S = Qh @ Kh^T : 16 k-steps, double-buffered K frags ----
        float sc[4][4];
#pragma unroll
        for (int n = 0; n < 4; n++)
#pragma unroll
            for (int j = 0; j < 4; j++) sc[n][j] = 0.f;

        {
            uint32_t ka[2][4], kb[2][4];
            ldm4(ka[0], bKh);
            ldm4(kb[0], bKh + 16 * KPB);
#pragma unroll
            for (int s = 0; s < 16; s++) {
                const int cur = s & 1, nxt = cur ^ 1;
                if (s < 15) {
                    ldm4(ka[nxt], bKh + (s + 1) * 32);
                    ldm4(kb[nxt], bKh + 16 * KPB + (s + 1) * 32);
                }
                mma16(sc[0], qf[s], ka[cur][0], ka[cur][1]);
                mma16(sc[1], qf[s], ka[cur][2], ka[cur][3]);
                mma16(sc[2], qf[s], kb[cur][0], kb[cur][1]);
                mma16(sc[3], qf[s], kb[cur][2], kb[cur][3]);
            }
        }

        // ---- softmax: p = exp(s/16), fp16 store, row sums ----
        {
            const int rowA = 16 * wq + g;
            const int colb = 32 * wk + 2 * tg;
            float ra = 0.f, rb = 0.f;
#pragma unroll
            for (int n = 0; n < 4; n++) {
                float p0 = __expf(sc[n][0] * SC);
                float p1 = __expf(sc[n][1] * SC);
                float p2 = __expf(sc[n][2] * SC);
                float p3 = __expf(sc[n][3] * SC);
                ra += p0 + p1;  rb += p2 + p3;
                *(half2*)&PhS[rowA * 72 + colb + 8 * n] =
                    __halves2half2(__float2half_rn(p0), __float2half_rn(p1));
                *(half2*)&PhS[(rowA + 8) * 72 + colb + 8 * n] =
                    __halves2half2(__float2half_rn(p2), __float2half_rn(p3));
            }
            ra += __shfl_xor_sync(0xffffffffu, ra, 1);
            ra += __shfl_xor_sync(0xffffffffu, ra, 2);
            rb += __shfl_xor_sync(0xffffffffu, rb, 1);
            rb += __shfl_xor_sync(0xffffffffu, rb, 2);
            lr0 += ra;  lr1 += rb;
        }
        __syncthreads();   // P visible; K reads done

        // ---- prefetch Kh(tI+1) (overlaps PV) ----
        if (tI + 1 < T) {
            const __half* kh = g_kh + ((size_t)bb * SEQ + (size_t)(tI + 1) * 64) * DIM;
#pragma unroll
            for (int it = 0; it < 8; it++) {
                int idx = it * 256 + tid, row = idx >> 5, u = idx & 31;
                cp16(sKH + (uint32_t)(row * KPB + u * 16), kh + (size_t)row * DIM + u * 8);
            }
        }
        asm volatile("cp.async.commit_group;\n" ::: "memory");

        asm volatile("cp.async.wait_group 1;\n" ::: "memory");  // V(tI) ready
        __syncthreads();

        // ---- PV: O += Ph*V ; double-buffered V frags ----
#pragma unroll
        for (int s = 0; s < 4; s++) {
            uint32_t ph[4];
            ldm4(ph, aPh + s * 32);
            uint32_t va[2][4];
            ldm4t(va[0], bV + (uint32_t)(s * 16 * KPB));
#pragma unroll
            for (int c = 0; c < 8; c++) {
                const int cur = c & 1, nxt = cur ^ 1;
                if (c < 7)
                    ldm4t(va[nxt], bV + (uint32_t)(s * 16 * KPB + (c + 1) * 32));
                mma16(o[2 * c],     ph, va[cur][0], va[cur][1]);
                mma16(o[2 * c + 1], ph, va[cur][2], va[cur][3]);
            }
        }
        __syncthreads();   // V reads done

        // ---- prefetch Vh(tI+1) (overlaps next S) ----
        if (tI + 1 < T) {
            const __half* vp = g_vh + ((size_t)bb * SEQ + (size_t)(tI + 1) * 64) * DIM;
#pragma unroll
            for (int it = 0; it < 8; it++) {
                int idx = it * 256 + tid, row = idx >> 5, u = idx & 31;
                cp16(sVH + (uint32_t)(row * KPB + u * 16), vp + (size_t)row * DIM + u * 8);
            }
        }
        asm volatile("cp.async.commit_group;\n" ::: "memory");
    }

    // ---- epilogue ----
    const int rowA = 16 * wq + g;
    if (tg == 0) {
        Ls[wk * 64 + rowA]     = lr0;
        Ls[wk * 64 + rowA + 8] = lr1;
    }
    __syncthreads();
    const float inv0 = 1.0f / (Ls[rowA]     + Ls[64 + rowA]);
    const float inv1 = 1.0f / (Ls[rowA + 8] + Ls[64 + rowA + 8]);

    const size_t rA = ((size_t)bb * SEQ + q0 + rowA) * DIM + 128 * wk + 2 * tg;
#pragma unroll
    for (int n = 0; n < 16; n++) {
        float2 vA = make_float2(o[n][0] * inv0, o[n][1] * inv0);
        float2 vB = make_float2(o[n][2] * inv1, o[n][3] * inv1);
        *(float2*)&out[rA + 8 * n]           = vA;
        *(float2*)&out[rA + 8 * DIM + 8 * n] = vB;
    }
}

// ---------------------------------------------------------------------------
extern "C" void kernel_launch(void* const* d_in, const int* in_sizes, int n_in,
                              void* d_out, int out_size)
{
    const float* x  = (const float*)d_in[0];
    const float* Wq = (const float*)d_in[1];
    const float* bq = (const float*)d_in[2];
    const float* Wk = (const float*)d_in[3];
    const float* bk = (const float*)d_in[4];
    const float* Wv = (const float*)d_in[5];
    const float* bv = (const float*)d_in[6];
    float* out = (float*)d_out;

    (void)in_sizes; (void)n_in; (void)out_size;

    split_kernel<<<2048, 256>>>(x, Wq, Wk, Wv);

    cudaFuncSetAttribute(qkv_mma_kernel,
                         cudaFuncAttributeMaxDynamicSharedMemorySize, QSMEM_BYTES);
    qkv_mma_kernel<<<dim3(12, 256), 256, QSMEM_BYTES>>>(bq, bk, bv);

    cudaFuncSetAttribute(attn_mma_kernel,
                         cudaFuncAttributeMaxDynamicSharedMemorySize, SMEM_BYTES);
    attn_mma_kernel<<<dim3(SEQ / 64, BATCH), 256, SMEM_BYTES>>>(out);
}

// round 13
// speedup vs baseline: 1.4427x; 1.2015x over previous
#include <cuda_runtime.h>
#include <cuda_fp16.h>
#include <math.h>
#include <stdint.h>

#define DIM 256
#define BATCH 4
#define SEQ 4096
#define M_TOTAL (BATCH * SEQ)

// fp16 scratch (allocation-free rule: device globals)
__device__ __half g_xh[M_TOTAL * DIM];
__device__ __half g_wh[3 * DIM * DIM];
__device__ __half g_qh[M_TOTAL * DIM];
__device__ __half g_kh[M_TOTAL * DIM];
__device__ __half g_vh[M_TOTAL * DIM];

// ---------------------------------------------------------------------------
// Kernel 0: convert x and W to fp16.
// ---------------------------------------------------------------------------
__global__ __launch_bounds__(256) void split_kernel(
    const float* __restrict__ x,
    const float* __restrict__ Wq, const float* __restrict__ Wk,
    const float* __restrict__ Wv)
{
    const int tid = blockIdx.x * blockDim.x + threadIdx.x;
    const int nt  = gridDim.x * blockDim.x;
    for (int i = tid; i < M_TOTAL * DIM / 4; i += nt) {
        float4 v = ((const float4*)x)[i];
        *(half2*)&g_xh[i * 4]     = __halves2half2(__float2half_rn(v.x), __float2half_rn(v.y));
        *(half2*)&g_xh[i * 4 + 2] = __halves2half2(__float2half_rn(v.z), __float2half_rn(v.w));
    }
    const float* Ws[3] = {Wq, Wk, Wv};
#pragma unroll
    for (int s = 0; s < 3; s++) {
        const float4* wp = (const float4*)Ws[s];
        for (int i = tid; i < DIM * DIM / 4; i += nt) {
            float4 v = wp[i];
            __half* o = g_wh + s * DIM * DIM + i * 4;
            *(half2*)(o)     = __halves2half2(__float2half_rn(v.x), __float2half_rn(v.y));
            *(half2*)(o + 2) = __halves2half2(__float2half_rn(v.z), __float2half_rn(v.w));
        }
    }
}

// ---------------------------------------------------------------------------
// Warp-MMA helpers (plain PTX — valid on compute_103)
// ---------------------------------------------------------------------------
__device__ __forceinline__ uint32_t smem_u32(const void* p) {
    return (uint32_t)__cvta_generic_to_shared(p);
}
__device__ __forceinline__ void cp16(uint32_t dst, const void* src) {
    asm volatile("cp.async.cg.shared.global [%0], [%1], 16;\n" :: "r"(dst), "l"(src));
}
__device__ __forceinline__ void ldm4(uint32_t r[4], uint32_t addr) {
    asm volatile("ldmatrix.sync.aligned.m8n8.x4.shared.b16 {%0,%1,%2,%3}, [%4];"
                 : "=r"(r[0]), "=r"(r[1]), "=r"(r[2]), "=r"(r[3]) : "r"(addr));
}
__device__ __forceinline__ void ldm4t(uint32_t r[4], uint32_t addr) {
    asm volatile("ldmatrix.sync.aligned.m8n8.x4.trans.shared.b16 {%0,%1,%2,%3}, [%4];"
                 : "=r"(r[0]), "=r"(r[1]), "=r"(r[2]), "=r"(r[3]) : "r"(addr));
}
__device__ __forceinline__ void mma16(float c[4], const uint32_t a[4],
                                      uint32_t b0, uint32_t b1) {
    asm volatile(
        "mma.sync.aligned.m16n8k16.row.col.f32.f16.f16.f32 "
        "{%0,%1,%2,%3}, {%4,%5,%6,%7}, {%8,%9}, {%0,%1,%2,%3};"
        : "+f"(c[0]), "+f"(c[1]), "+f"(c[2]), "+f"(c[3])
        : "r"(a[0]), "r"(a[1]), "r"(a[2]), "r"(a[3]), "r"(b0), "r"(b1));
}

#define KPB 528     // 256-half row pitch in bytes (+16B pad)
#define PPB 144     // 64-half row pitch in bytes (+16B pad)

// ---------------------------------------------------------------------------
// Kernel 1: QKV projection, single-term fp16 MMA.
//   y = Xh*Wh + bias   -> qh / kh / vh (fp16)
// (fp16-RN input quantization measured ~2e-5 each in quadrature — R9 data)
// ---------------------------------------------------------------------------
#define QSM_XH 0
#define QSM_WH (QSM_XH + 64 * KPB)
#define QSMEM_BYTES (QSM_WH + 64 * KPB)   // 67584

extern __shared__ char smem_raw[];

__global__ __launch_bounds__(256, 1) void qkv_mma_kernel(
    const float* __restrict__ bq, const float* __restrict__ bk,
    const float* __restrict__ bv)
{
    const int tid = threadIdx.x;
    const int w = tid >> 5, lane = tid & 31;
    const int g = lane >> 2, tg = lane & 3;
    const int wq = w & 3, wn = w >> 2;
    const int wsel = blockIdx.x >> 2;
    const int n0   = (blockIdx.x & 3) * 64;
    const int m0   = blockIdx.y * 64;
    const float* bias = (wsel == 0) ? bq : (wsel == 1) ? bk : bv;

    const uint32_t sXH = smem_u32(smem_raw + QSM_XH);
    const uint32_t sWH = smem_u32(smem_raw + QSM_WH);

    {
        const __half* wh = g_wh + (size_t)wsel * DIM * DIM + (size_t)n0 * DIM;
#pragma unroll
        for (int it = 0; it < 8; it++) {
            int idx = it * 256 + tid, row = idx >> 5, u = idx & 31;
            uint32_t so = (uint32_t)(row * KPB + u * 16);
            cp16(sXH + so, g_xh + (size_t)(m0 + row) * DIM + u * 8);
            cp16(sWH + so, wh + (size_t)row * DIM + u * 8);
        }
    }
    asm volatile("cp.async.commit_group;\n" ::: "memory");
    asm volatile("cp.async.wait_group 0;\n" ::: "memory");
    __syncthreads();

    const int mm = lane >> 3, rr = lane & 7;
    const uint32_t aXh = sXH + (16 * wq + ((mm & 1) << 3) + rr) * KPB + (mm >> 1) * 16;
    const uint32_t bWh = sWH + (32 * wn + ((mm >> 1) << 3) + rr) * KPB + (mm & 1) * 16;

    float c[4][4];
#pragma unroll
    for (int n = 0; n < 4; n++)
#pragma unroll
        for (int j = 0; j < 4; j++) c[n][j] = 0.f;

#pragma unroll 8
    for (int s = 0; s < 16; s++) {
        uint32_t xh[4], h0[4], h1[4];
        ldm4(xh, aXh + s * 32);
        ldm4(h0, bWh + s * 32);
        ldm4(h1, bWh + 16 * KPB + s * 32);
        mma16(c[0], xh, h0[0], h0[1]);
        mma16(c[1], xh, h0[2], h0[3]);
        mma16(c[2], xh, h1[0], h1[1]);
        mma16(c[3], xh, h1[2], h1[3]);
    }

    __half* dst = (wsel == 0) ? g_qh : (wsel == 1) ? g_kh : g_vh;
    const int colg = n0 + 32 * wn + 2 * tg;
#pragma unroll
    for (int n = 0; n < 4; n++) {
        int col = colg + 8 * n;
        float b0 = bias[col], b1 = bias[col + 1];
#pragma unroll
        for (int h = 0; h < 2; h++) {
            int row = m0 + 16 * wq + g + 8 * h;
            float y0 = c[n][2 * h] + b0, y1 = c[n][2 * h + 1] + b1;
            *(half2*)&dst[(size_t)row * DIM + col] =
                __halves2half2(__float2half_rn(y0), __float2half_rn(y1));
        }
    }
}

// ---------------------------------------------------------------------------
// Kernel 2: flash attention, fp16 m16n8k16, 8 warps.
//   - Q A-fragments register-resident across all 64 key tiles
//   - K and V smem double-buffered (ping-pong): prefetch(t+1) issues at the
//     TOP of tile t into the idle buffer -> loads overlap S+softmax+PV and
//     syncthreads drop to 2 per tile.
//   - l row-sums accumulated per-thread; shuffle-reduced once in epilogue.
// CTA = (batch, 64 queries); 64-key tiles.
//   S phase : warp grid 4q x 2k, warp tile 16q x 32k.
//   PV phase: warp grid 4q x 2d, warp tile 16q x 128d.
// ---------------------------------------------------------------------------
#define TBUF (64 * KPB)                    // 33792 per K/V buffer
#define SM_QH 0
#define SM_KH (SM_QH + TBUF)               // 2 buffers
#define SM_VH (SM_KH + 2 * TBUF)           // 2 buffers
#define SM_PH (SM_VH + 2 * TBUF)
#define SM_LS (SM_PH + 64 * PPB)
#define SMEM_BYTES (SM_LS + 2 * 64 * 4)    // 178688

__global__ __launch_bounds__(256, 1) void attn_mma_kernel(float* __restrict__ out)
{
    const int tid  = threadIdx.x;
    const int w    = tid >> 5;
    const int lane = tid & 31;
    const int g    = lane >> 2;
    const int tg   = lane & 3;
    const int wq   = w & 3;          // q strip (16 rows)
    const int wk   = w >> 2;         // S: 32-key strip ; PV: 128-d half
    const int bb   = blockIdx.y;
    const int q0   = blockIdx.x * 64;
    const size_t qbase = ((size_t)bb * SEQ + q0) * DIM;

    const uint32_t sQH = smem_u32(smem_raw + SM_QH);
    const uint32_t sKH = smem_u32(smem_raw + SM_KH);
    const uint32_t sVH = smem_u32(smem_raw + SM_VH);
    const uint32_t sPH = smem_u32(smem_raw + SM_PH);
    __half* PhS = (__half*)(smem_raw + SM_PH);
    float*  Ls  = (float*)(smem_raw + SM_LS);

    const int mm = lane >> 3, rr = lane & 7;
    const uint32_t aQh = sQH + (16 * wq + ((mm & 1) << 3) + rr) * KPB + (mm >> 1) * 16;
    const uint32_t oKh = (uint32_t)((32 * wk + ((mm >> 1) << 3) + rr) * KPB + (mm & 1) * 16);
    const uint32_t aPh = sPH + (16 * wq + ((mm & 1) << 3) + rr) * PPB + (mm >> 1) * 16;
    const uint32_t oV  = (uint32_t)((((mm & 1) << 3) + rr) * KPB + 256 * wk + (mm >> 1) * 16);

    // ---- prologue: one group = {Qh, Kh(0)->buf0, Vh(0)->buf0} ----
    {
        const __half* kh = g_kh + ((size_t)bb * SEQ) * DIM;
        const __half* vp = g_vh + ((size_t)bb * SEQ) * DIM;
#pragma unroll
        for (int it = 0; it < 8; it++) {
            int idx = it * 256 + tid, row = idx >> 5, u = idx & 31;
            uint32_t so = (uint32_t)(row * KPB + u * 16);
            size_t   go = (size_t)row * DIM + u * 8;
            cp16(sQH + so, g_qh + qbase + go);
            cp16(sKH + so, kh + go);
            cp16(sVH + so, vp + go);
        }
    }
    asm volatile("cp.async.commit_group;\n" ::: "memory");

    float o[16][4];
#pragma unroll
    for (int n = 0; n < 16; n++)
#pragma unroll
        for (int j = 0; j < 4; j++) o[n][j] = 0.f;
    float lr0 = 0.f, lr1 = 0.f;

    uint32_t qf[16][4];   // register-resident Q A-fragments

    const int T = SEQ / 64;
    const float SC = 0.0625f;

    for (int tI = 0; tI < T; tI++) {
        // group committed at tile tI-1 (K,V for tI) done
        asm volatile("cp.async.wait_group 0;\n" ::: "memory");
        __syncthreads();

        if (tI == 0) {   // hoist Q fragments once
#pragma unroll
            for (int s = 0; s < 16; s++) ldm4(qf[s], aQh + s * 32);
        }

        const uint32_t buf  = (uint32_t)(tI & 1) * TBUF;
        const uint32_t nbuf = buf ^ TBUF;

        // ---- prefetch K(tI+1), V(tI+1) into idle buffers (overlaps S+PV) ----
        if (tI + 1 < T) {
            const __half* kh = g_kh + ((size_t)bb * SEQ + (size_t)(tI + 1) * 64) * DIM;
            const __half* vp = g_vh + ((size_t)bb * SEQ + (size_t)(tI + 1) * 64) * DIM;
#pragma unroll
            for (int it = 0; it < 8; it++) {
                int idx = it * 256 + tid, row = idx >> 5, u = idx & 31;
                uint32_t so = (uint32_t)(row * KPB + u * 16);
                size_t   go = (size_t)row * DIM + u * 8;
                cp16(sKH + nbuf + so, kh + go);
                cp16(sVH + nbuf + so, vp + go);
            }
        }
        asm volatile("cp.async.commit_group;\n" ::: "memory");

        // ---- S = Qh @ Kh^T : 16 k-steps, double-buffered K frags ----
        const uint32_t bKh = sKH + buf + oKh;
        float sc[4][4];
#pragma unroll
        for (int n = 0; n < 4; n++)
#pragma unroll
            for (int j = 0; j < 4; j++) sc[n][j] = 0.f;

        {
            uint32_t ka[2][4], kb[2][4];
            ldm4(ka[0], bKh);
            ldm4(kb[0], bKh + 16 * KPB);
#pragma unroll
            for (int s = 0; s < 16; s++) {
                const int cur = s & 1, nxt = cur ^ 1;
                if (s < 15) {
                    ldm4(ka[nxt], bKh + (s + 1) * 32);
                    ldm4(kb[nxt], bKh + 16 * KPB + (s + 1) * 32);
                }
                mma16(sc[0], qf[s], ka[cur][0], ka[cur][1]);
                mma16(sc[1], qf[s], ka[cur][2], ka[cur][3]);
                mma16(sc[2], qf[s], kb[cur][0], kb[cur][1]);
                mma16(sc[3], qf[s], kb[cur][2], kb[cur][3]);
            }
        }

        // ---- softmax: p = exp(s/16), fp16 store; defer row reductions ----
        {
            const int rowA = 16 * wq + g;
            const int colb = 32 * wk + 2 * tg;
#pragma unroll
            for (int n = 0; n < 4; n++) {
                float p0 = __expf(sc[n][0] * SC);
                float p1 = __expf(sc[n][1] * SC);
                float p2 = __expf(sc[n][2] * SC);
                float p3 = __expf(sc[n][3] * SC);
                lr0 += p0 + p1;  lr1 += p2 + p3;
                *(half2*)&PhS[rowA * 72 + colb + 8 * n] =
                    __halves2half2(__float2half_rn(p0), __float2half_rn(p1));
                *(half2*)&PhS[(rowA + 8) * 72 + colb + 8 * n] =
                    __halves2half2(__float2half_rn(p2), __float2half_rn(p3));
            }
        }
        __syncthreads();   // P visible to all warps

        // ---- PV: O += Ph*V ; double-buffered V frags ----
        const uint32_t bV = sVH + buf + oV;
#pragma unroll
        for (int s = 0; s < 4; s++) {
            uint32_t ph[4];
            ldm4(ph, aPh + s * 32);
            uint32_t va[2][4];
            ldm4t(va[0], bV + (uint32_t)(s * 16 * KPB));
#pragma unroll
            for (int c = 0; c < 8; c++) {
                const int cur = c & 1, nxt = cur ^ 1;
                if (c < 7)
                    ldm4t(va[nxt], bV + (uint32_t)(s * 16 * KPB + (c + 1) * 32));
                mma16(o[2 * c],     ph, va[cur][0], va[cur][1]);
                mma16(o[2 * c + 1], ph, va[cur][2], va[cur][3]);
            }
        }
        // no sync needed: next tile's writes go to the other K/V buffers,
        // and P is re-written only after the top-of-loop sync.
    }

    // ---- epilogue: reduce l once, combine across k-strips, store ----
    lr0 += __shfl_xor_sync(0xffffffffu, lr0, 1);
    lr0 += __shfl_xor_sync(0xffffffffu, lr0, 2);
    lr1 += __shfl_xor_sync(0xffffffffu, lr1, 1);
    lr1 += __shfl_xor_sync(0xffffffffu, lr1, 2);

    const int rowA = 16 * wq + g;
    if (tg == 0) {
        Ls[wk * 64 + rowA]     = lr0;
        Ls[wk * 64 + rowA + 8] = lr1;
    }
    __syncthreads();
    const float inv0 = 1.0f / (Ls[rowA]     + Ls[64 + rowA]);
    const float inv1 = 1.0f / (Ls[rowA + 8] + Ls[64 + rowA + 8]);

    const size_t rA = ((size_t)bb * SEQ + q0 + rowA) * DIM + 128 * wk + 2 * tg;
#pragma unroll
    for (int n = 0; n < 16; n++) {
        float2 vA = make_float2(o[n][0] * inv0, o[n][1] * inv0);
        float2 vB = make_float2(o[n][2] * inv1, o[n][3] * inv1);
        *(float2*)&out[rA + 8 * n]           = vA;
        *(float2*)&out[rA + 8 * DIM + 8 * n] = vB;
    }
}

// ---------------------------------------------------------------------------
extern "C" void kernel_launch(void* const* d_in, const int* in_sizes, int n_in,
                              void* d_out, int out_size)
{
    const float* x  = (const float*)d_in[0];
    const float* Wq = (const float*)d_in[1];
    const float* bq = (const float*)d_in[2];
    const float* Wk = (const float*)d_in[3];
    const float* bk = (const float*)d_in[4];
    const float* Wv = (const float*)d_in[5];
    const float* bv = (const float*)d_in[6];
    float* out = (float*)d_out;

    (void)in_sizes; (void)n_in; (void)out_size;

    split_kernel<<<2048, 256>>>(x, Wq, Wk, Wv);

    cudaFuncSetAttribute(qkv_mma_kernel,
                         cudaFuncAttributeMaxDynamicSharedMemorySize, QSMEM_BYTES);
    qkv_mma_kernel<<<dim3(12, 256), 256, QSMEM_BYTES>>>(bq, bk, bv);

    cudaFuncSetAttribute(attn_mma_kernel,
                         cudaFuncAttributeMaxDynamicSharedMemorySize, SMEM_BYTES);
    attn_mma_kernel<<<dim3(SEQ / 64, BATCH), 256, SMEM_BYTES>>>(out);
}

// round 14
// speedup vs baseline: 1.4809x; 1.0265x over previous
#include <cuda_runtime.h>
#include <cuda_fp16.h>
#include <math.h>
#include <stdint.h>

#define DIM 256
#define BATCH 4
#define SEQ 4096
#define M_TOTAL (BATCH * SEQ)

// fp16 scratch (allocation-free rule: device globals)
__device__ __half g_xh[M_TOTAL * DIM];
__device__ __half g_wh[3 * DIM * DIM];
__device__ __half g_qh[M_TOTAL * DIM];
__device__ __half g_kh[M_TOTAL * DIM];
__device__ __half g_vh[M_TOTAL * DIM];

// ---------------------------------------------------------------------------
// Kernel 0: convert x and W to fp16.
// ---------------------------------------------------------------------------
__global__ __launch_bounds__(256) void split_kernel(
    const float* __restrict__ x,
    const float* __restrict__ Wq, const float* __restrict__ Wk,
    const float* __restrict__ Wv)
{
    const int tid = blockIdx.x * blockDim.x + threadIdx.x;
    const int nt  = gridDim.x * blockDim.x;
    for (int i = tid; i < M_TOTAL * DIM / 4; i += nt) {
        float4 v = ((const float4*)x)[i];
        *(half2*)&g_xh[i * 4]     = __halves2half2(__float2half_rn(v.x), __float2half_rn(v.y));
        *(half2*)&g_xh[i * 4 + 2] = __halves2half2(__float2half_rn(v.z), __float2half_rn(v.w));
    }
    const float* Ws[3] = {Wq, Wk, Wv};
#pragma unroll
    for (int s = 0; s < 3; s++) {
        const float4* wp = (const float4*)Ws[s];
        for (int i = tid; i < DIM * DIM / 4; i += nt) {
            float4 v = wp[i];
            __half* o = g_wh + s * DIM * DIM + i * 4;
            *(half2*)(o)     = __halves2half2(__float2half_rn(v.x), __float2half_rn(v.y));
            *(half2*)(o + 2) = __halves2half2(__float2half_rn(v.z), __float2half_rn(v.w));
        }
    }
}

// ---------------------------------------------------------------------------
// Warp-MMA helpers (plain PTX — valid on compute_103)
// ---------------------------------------------------------------------------
__device__ __forceinline__ uint32_t smem_u32(const void* p) {
    return (uint32_t)__cvta_generic_to_shared(p);
}
__device__ __forceinline__ void cp16(uint32_t dst, const void* src) {
    asm volatile("cp.async.cg.shared.global [%0], [%1], 16;\n" :: "r"(dst), "l"(src));
}
__device__ __forceinline__ void ldm4(uint32_t r[4], uint32_t addr) {
    asm volatile("ldmatrix.sync.aligned.m8n8.x4.shared.b16 {%0,%1,%2,%3}, [%4];"
                 : "=r"(r[0]), "=r"(r[1]), "=r"(r[2]), "=r"(r[3]) : "r"(addr));
}
__device__ __forceinline__ void ldm4t(uint32_t r[4], uint32_t addr) {
    asm volatile("ldmatrix.sync.aligned.m8n8.x4.trans.shared.b16 {%0,%1,%2,%3}, [%4];"
                 : "=r"(r[0]), "=r"(r[1]), "=r"(r[2]), "=r"(r[3]) : "r"(addr));
}
__device__ __forceinline__ void mma16(float c[4], const uint32_t a[4],
                                      uint32_t b0, uint32_t b1) {
    asm volatile(
        "mma.sync.aligned.m16n8k16.row.col.f32.f16.f16.f32 "
        "{%0,%1,%2,%3}, {%4,%5,%6,%7}, {%8,%9}, {%0,%1,%2,%3};"
        : "+f"(c[0]), "+f"(c[1]), "+f"(c[2]), "+f"(c[3])
        : "r"(a[0]), "r"(a[1]), "r"(a[2]), "r"(a[3]), "r"(b0), "r"(b1));
}

#define KPB 528     // 256-half row pitch in bytes (+16B pad)
#define PPB 144     // 64-half row pitch in bytes (+16B pad)

// ---------------------------------------------------------------------------
// Kernel 1: QKV projection, single-term fp16 MMA, 128m x 64n CTA tile.
//   y = Xh*Wh + bias   -> qh / kh / vh (fp16)
// Warp tile 32m x 32n: per k16-step 4 ldm4 : 8 MMA (ldm per output halved
// vs the old 64x64 tiling).
// ---------------------------------------------------------------------------
#define QSM_XH 0
#define QSM_WH (QSM_XH + 128 * KPB)
#define QSMEM_BYTES (QSM_WH + 64 * KPB)   // 101376

extern __shared__ char smem_raw[];

__global__ __launch_bounds__(256, 1) void qkv_mma_kernel(
    const float* __restrict__ bq, const float* __restrict__ bk,
    const float* __restrict__ bv)
{
    const int tid = threadIdx.x;
    const int w = tid >> 5, lane = tid & 31;
    const int g = lane >> 2, tg = lane & 3;
    const int wm = w & 3, wn = w >> 2;
    const int wsel = blockIdx.x >> 2;
    const int n0   = (blockIdx.x & 3) * 64;
    const int m0   = blockIdx.y * 128;
    const float* bias = (wsel == 0) ? bq : (wsel == 1) ? bk : bv;

    const uint32_t sXH = smem_u32(smem_raw + QSM_XH);
    const uint32_t sWH = smem_u32(smem_raw + QSM_WH);

    {
#pragma unroll
        for (int it = 0; it < 16; it++) {   // X: 128 rows
            int idx = it * 256 + tid, row = idx >> 5, u = idx & 31;
            cp16(sXH + (uint32_t)(row * KPB + u * 16),
                 g_xh + (size_t)(m0 + row) * DIM + u * 8);
        }
        const __half* wh = g_wh + (size_t)wsel * DIM * DIM + (size_t)n0 * DIM;
#pragma unroll
        for (int it = 0; it < 8; it++) {    // W: 64 rows
            int idx = it * 256 + tid, row = idx >> 5, u = idx & 31;
            cp16(sWH + (uint32_t)(row * KPB + u * 16), wh + (size_t)row * DIM + u * 8);
        }
    }
    asm volatile("cp.async.commit_group;\n" ::: "memory");
    asm volatile("cp.async.wait_group 0;\n" ::: "memory");
    __syncthreads();

    const int mm = lane >> 3, rr = lane & 7;
    const uint32_t aX0 = sXH + (32 * wm + ((mm & 1) << 3) + rr) * KPB + (mm >> 1) * 16;
    const uint32_t aX1 = aX0 + 16 * KPB;
    const uint32_t bW  = sWH + (32 * wn + ((mm >> 1) << 3) + rr) * KPB + (mm & 1) * 16;

    float c[2][4][4];
#pragma unroll
    for (int m = 0; m < 2; m++)
#pragma unroll
        for (int n = 0; n < 4; n++)
#pragma unroll
            for (int j = 0; j < 4; j++) c[m][n][j] = 0.f;

#pragma unroll 8
    for (int s = 0; s < 16; s++) {
        uint32_t xa[4], xb[4], b0[4], b1[4];
        ldm4(xa, aX0 + s * 32);
        ldm4(xb, aX1 + s * 32);
        ldm4(b0, bW + s * 32);
        ldm4(b1, bW + 16 * KPB + s * 32);
        mma16(c[0][0], xa, b0[0], b0[1]);
        mma16(c[0][1], xa, b0[2], b0[3]);
        mma16(c[0][2], xa, b1[0], b1[1]);
        mma16(c[0][3], xa, b1[2], b1[3]);
        mma16(c[1][0], xb, b0[0], b0[1]);
        mma16(c[1][1], xb, b0[2], b0[3]);
        mma16(c[1][2], xb, b1[0], b1[1]);
        mma16(c[1][3], xb, b1[2], b1[3]);
    }

    __half* dst = (wsel == 0) ? g_qh : (wsel == 1) ? g_kh : g_vh;
    const int colg = n0 + 32 * wn + 2 * tg;
#pragma unroll
    for (int m = 0; m < 2; m++) {
#pragma unroll
        for (int n = 0; n < 4; n++) {
            int col = colg + 8 * n;
            float b0 = bias[col], b1 = bias[col + 1];
#pragma unroll
            for (int h = 0; h < 2; h++) {
                int row = m0 + 32 * wm + 16 * m + g + 8 * h;
                float y0 = c[m][n][2 * h] + b0, y1 = c[m][n][2 * h + 1] + b1;
                *(half2*)&dst[(size_t)row * DIM + col] =
                    __halves2half2(__float2half_rn(y0), __float2half_rn(y1));
            }
        }
    }
}

// ---------------------------------------------------------------------------
// Kernel 2: flash attention, fp16 m16n8k16, 8 warps.
//   - Q A-fragments register-resident; K/V smem double-buffered (R13 WIN)
//   - S  phase: warp grid 4q x 2k (16q x 32k), Q resident
//   - PV phase: warp grid 2q x 4d (32q x 64d) — V frag redundancy 4 -> 2,
//     CTA PV ldm4 288 -> 192 per tile
//   - l row-sums deferred to epilogue
// CTA = (batch, 64 queries); 64-key tiles.
// ---------------------------------------------------------------------------
#define TBUF (64 * KPB)                    // 33792 per K/V buffer
#define SM_QH 0
#define SM_KH (SM_QH + TBUF)               // 2 buffers
#define SM_VH (SM_KH + 2 * TBUF)           // 2 buffers
#define SM_PH (SM_VH + 2 * TBUF)
#define SM_LS (SM_PH + 64 * PPB)
#define SMEM_BYTES (SM_LS + 2 * 64 * 4)    // 178688

__global__ __launch_bounds__(256, 1) void attn_mma_kernel(float* __restrict__ out)
{
    const int tid  = threadIdx.x;
    const int w    = tid >> 5;
    const int lane = tid & 31;
    const int g    = lane >> 2;
    const int tg   = lane & 3;
    const int wq   = w & 3;          // S: q strip (16 rows)
    const int wk   = w >> 2;         // S: 32-key strip
    const int pq   = w & 1;          // PV: 32-row q strip
    const int pd   = w >> 1;         // PV: 64-col d strip
    const int bb   = blockIdx.y;
    const int q0   = blockIdx.x * 64;
    const size_t qbase = ((size_t)bb * SEQ + q0) * DIM;

    const uint32_t sQH = smem_u32(smem_raw + SM_QH);
    const uint32_t sKH = smem_u32(smem_raw + SM_KH);
    const uint32_t sVH = smem_u32(smem_raw + SM_VH);
    const uint32_t sPH = smem_u32(smem_raw + SM_PH);
    __half* PhS = (__half*)(smem_raw + SM_PH);
    float*  Ls  = (float*)(smem_raw + SM_LS);

    const int mm = lane >> 3, rr = lane & 7;
    const uint32_t aQh = sQH + (16 * wq + ((mm & 1) << 3) + rr) * KPB + (mm >> 1) * 16;
    const uint32_t oKh = (uint32_t)((32 * wk + ((mm >> 1) << 3) + rr) * KPB + (mm & 1) * 16);
    // PV: P A-frags rows 32*pq..+31 (two 16-row groups)
    const uint32_t aPh = sPH + (32 * pq + ((mm & 1) << 3) + rr) * PPB + (mm >> 1) * 16;
    // PV: V B-frags, d strip 64*pd (128 bytes)
    const uint32_t oV  = (uint32_t)((((mm & 1) << 3) + rr) * KPB + 128 * pd + (mm >> 1) * 16);

    // ---- prologue: one group = {Qh, Kh(0)->buf0, Vh(0)->buf0} ----
    {
        const __half* kh = g_kh + ((size_t)bb * SEQ) * DIM;
        const __half* vp = g_vh + ((size_t)bb * SEQ) * DIM;
#pragma unroll
        for (int it = 0; it < 8; it++) {
            int idx = it * 256 + tid, row = idx >> 5, u = idx & 31;
            uint32_t so = (uint32_t)(row * KPB + u * 16);
            size_t   go = (size_t)row * DIM + u * 8;
            cp16(sQH + so, g_qh + qbase + go);
            cp16(sKH + so, kh + go);
            cp16(sVH + so, vp + go);
        }
    }
    asm volatile("cp.async.commit_group;\n" ::: "memory");

    float o2[2][8][4];
#pragma unroll
    for (int m = 0; m < 2; m++)
#pragma unroll
        for (int n = 0; n < 8; n++)
#pragma unroll
            for (int j = 0; j < 4; j++) o2[m][n][j] = 0.f;
    float lr0 = 0.f, lr1 = 0.f;

    uint32_t qf[16][4];   // register-resident Q A-fragments

    const int T = SEQ / 64;
    const float SC = 0.0625f;

    for (int tI = 0; tI < T; tI++) {
        asm volatile("cp.async.wait_group 0;\n" ::: "memory");
        __syncthreads();

        if (tI == 0) {
#pragma unroll
            for (int s = 0; s < 16; s++) ldm4(qf[s], aQh + s * 32);
        }

        const uint32_t buf  = (uint32_t)(tI & 1) * TBUF;
        const uint32_t nbuf = buf ^ TBUF;

        // ---- prefetch K(tI+1), V(tI+1) into idle buffers ----
        if (tI + 1 < T) {
            const __half* kh = g_kh + ((size_t)bb * SEQ + (size_t)(tI + 1) * 64) * DIM;
            const __half* vp = g_vh + ((size_t)bb * SEQ + (size_t)(tI + 1) * 64) * DIM;
#pragma unroll
            for (int it = 0; it < 8; it++) {
                int idx = it * 256 + tid, row = idx >> 5, u = idx & 31;
                uint32_t so = (uint32_t)(row * KPB + u * 16);
                size_t   go = (size_t)row * DIM + u * 8;
                cp16(sKH + nbuf + so, kh + go);
                cp16(sVH + nbuf + so, vp + go);
            }
        }
        asm volatile("cp.async.commit_group;\n" ::: "memory");

        // ---- S = Qh @ Kh^T : 16 k-steps, double-buffered K frags ----
        const uint32_t bKh = sKH + buf + oKh;
        float sc[4][4];
#pragma unroll
        for (int n = 0; n < 4; n++)
#pragma unroll
            for (int j = 0; j < 4; j++) sc[n][j] = 0.f;

        {
            uint32_t ka[2][4], kb[2][4];
            ldm4(ka[0], bKh);
            ldm4(kb[0], bKh + 16 * KPB);
#pragma unroll
            for (int s = 0; s < 16; s++) {
                const int cur = s & 1, nxt = cur ^ 1;
                if (s < 15) {
                    ldm4(ka[nxt], bKh + (s + 1) * 32);
                    ldm4(kb[nxt], bKh + 16 * KPB + (s + 1) * 32);
                }
                mma16(sc[0], qf[s], ka[cur][0], ka[cur][1]);
                mma16(sc[1], qf[s], ka[cur][2], ka[cur][3]);
                mma16(sc[2], qf[s], kb[cur][0], kb[cur][1]);
                mma16(sc[3], qf[s], kb[cur][2], kb[cur][3]);
            }
        }

        // ---- softmax: p = exp(s/16), fp16 store; defer row reductions ----
        {
            const int rowA = 16 * wq + g;
            const int colb = 32 * wk + 2 * tg;
#pragma unroll
            for (int n = 0; n < 4; n++) {
                float p0 = __expf(sc[n][0] * SC);
                float p1 = __expf(sc[n][1] * SC);
                float p2 = __expf(sc[n][2] * SC);
                float p3 = __expf(sc[n][3] * SC);
                lr0 += p0 + p1;  lr1 += p2 + p3;
                *(half2*)&PhS[rowA * 72 + colb + 8 * n] =
                    __halves2half2(__float2half_rn(p0), __float2half_rn(p1));
                *(half2*)&PhS[(rowA + 8) * 72 + colb + 8 * n] =
                    __halves2half2(__float2half_rn(p2), __float2half_rn(p3));
            }
        }
        __syncthreads();   // P visible to all warps

        // ---- PV: O += Ph*V ; warp tile 32q x 64d ----
        const uint32_t bV = sVH + buf + oV;
#pragma unroll
        for (int s = 0; s < 4; s++) {
            uint32_t pa[2][4];
            ldm4(pa[0], aPh + s * 32);
            ldm4(pa[1], aPh + 16 * PPB + s * 32);
            uint32_t vb[2][4];
            ldm4t(vb[0], bV + (uint32_t)(s * 16 * KPB));
#pragma unroll
            for (int cc = 0; cc < 4; cc++) {
                const int cur = cc & 1, nxt = cur ^ 1;
                if (cc < 3)
                    ldm4t(vb[nxt], bV + (uint32_t)(s * 16 * KPB + (cc + 1) * 32));
                mma16(o2[0][2 * cc],     pa[0], vb[cur][0], vb[cur][1]);
                mma16(o2[0][2 * cc + 1], pa[0], vb[cur][2], vb[cur][3]);
                mma16(o2[1][2 * cc],     pa[1], vb[cur][0], vb[cur][1]);
                mma16(o2[1][2 * cc + 1], pa[1], vb[cur][2], vb[cur][3]);
            }
        }
        // no tail sync: next tile writes other K/V buffers; P rewritten only
        // after the top-of-loop sync.
    }

    // ---- epilogue: reduce l once, combine across k-strips, store ----
    lr0 += __shfl_xor_sync(0xffffffffu, lr0, 1);
    lr0 += __shfl_xor_sync(0xffffffffu, lr0, 2);
    lr1 += __shfl_xor_sync(0xffffffffu, lr1, 1);
    lr1 += __shfl_xor_sync(0xffffffffu, lr1, 2);

    const int rowS = 16 * wq + g;
    if (tg == 0) {
        Ls[wk * 64 + rowS]     = lr0;
        Ls[wk * 64 + rowS + 8] = lr1;
    }
    __syncthreads();

    const int r0 = 32 * pq + g;        // PV m=0 rows r0, r0+8
    const int r1 = 32 * pq + 16 + g;   // PV m=1 rows r1, r1+8
    const float i00 = 1.0f / (Ls[r0]     + Ls[64 + r0]);
    const float i01 = 1.0f / (Ls[r0 + 8] + Ls[64 + r0 + 8]);
    const float i10 = 1.0f / (Ls[r1]     + Ls[64 + r1]);
    const float i11 = 1.0f / (Ls[r1 + 8] + Ls[64 + r1 + 8]);

#pragma unroll
    for (int m = 0; m < 2; m++) {
        const float invA = m ? i10 : i00;
        const float invB = m ? i11 : i01;
        const size_t base = ((size_t)bb * SEQ + q0 + 32 * pq + 16 * m + g) * DIM
                          + 64 * pd + 2 * tg;
#pragma unroll
        for (int cc = 0; cc < 8; cc++) {
            float2 vA = make_float2(o2[m][cc][0] * invA, o2[m][cc][1] * invA);
            float2 vB = make_float2(o2[m][cc][2] * invB, o2[m][cc][3] * invB);
            *(float2*)&out[base + 8 * cc]           = vA;
            *(float2*)&out[base + 8 * DIM + 8 * cc] = vB;
        }
    }
}

// ---------------------------------------------------------------------------
extern "C" void kernel_launch(void* const* d_in, const int* in_sizes, int n_in,
                              void* d_out, int out_size)
{
    const float* x  = (const float*)d_in[0];
    const float* Wq = (const float*)d_in[1];
    const float* bq = (const float*)d_in[2];
    const float* Wk = (const float*)d_in[3];
    const float* bk = (const float*)d_in[4];
    const float* Wv = (const float*)d_in[5];
    const float* bv = (const float*)d_in[6];
    float* out = (float*)d_out;

    (void)in_sizes; (void)n_in; (void)out_size;

    split_kernel<<<2048, 256>>>(x, Wq, Wk, Wv);

    cudaFuncSetAttribute(qkv_mma_kernel,
                         cudaFuncAttributeMaxDynamicSharedMemorySize, QSMEM_BYTES);
    qkv_mma_kernel<<<dim3(12, 128), 256, QSMEM_BYTES>>>(bq, bk, bv);

    cudaFuncSetAttribute(attn_mma_kernel,
                         cudaFuncAttributeMaxDynamicSharedMemorySize, SMEM_BYTES);
    attn_mma_kernel<<<dim3(SEQ / 64, BATCH), 256, SMEM_BYTES>>>(out);
}

// round 15
// speedup vs baseline: 1.4911x; 1.0069x over previous
#include <cuda_runtime.h>
#include <cuda_fp16.h>
#include <math.h>
#include <stdint.h>

#define DIM 256
#define BATCH 4
#define SEQ 4096
#define M_TOTAL (BATCH * SEQ)

// fp16 scratch (allocation-free rule: device globals)
__device__ __half g_xh[M_TOTAL * DIM];
__device__ __half g_wh[3 * DIM * DIM];
__device__ __half g_qh[M_TOTAL * DIM];
__device__ __half g_kh[M_TOTAL * DIM];
__device__ __half g_vh[M_TOTAL * DIM];

// ---------------------------------------------------------------------------
// Kernel 0: convert x and W to fp16.
// ---------------------------------------------------------------------------
__global__ __launch_bounds__(256) void split_kernel(
    const float* __restrict__ x,
    const float* __restrict__ Wq, const float* __restrict__ Wk,
    const float* __restrict__ Wv)
{
    const int tid = blockIdx.x * blockDim.x + threadIdx.x;
    const int nt  = gridDim.x * blockDim.x;
    for (int i = tid; i < M_TOTAL * DIM / 4; i += nt) {
        float4 v = ((const float4*)x)[i];
        *(half2*)&g_xh[i * 4]     = __halves2half2(__float2half_rn(v.x), __float2half_rn(v.y));
        *(half2*)&g_xh[i * 4 + 2] = __halves2half2(__float2half_rn(v.z), __float2half_rn(v.w));
    }
    const float* Ws[3] = {Wq, Wk, Wv};
#pragma unroll
    for (int s = 0; s < 3; s++) {
        const float4* wp = (const float4*)Ws[s];
        for (int i = tid; i < DIM * DIM / 4; i += nt) {
            float4 v = wp[i];
            __half* o = g_wh + s * DIM * DIM + i * 4;
            *(half2*)(o)     = __halves2half2(__float2half_rn(v.x), __float2half_rn(v.y));
            *(half2*)(o + 2) = __halves2half2(__float2half_rn(v.z), __float2half_rn(v.w));
        }
    }
}

// ---------------------------------------------------------------------------
// Warp-MMA helpers (plain PTX — valid on compute_103)
// ---------------------------------------------------------------------------
__device__ __forceinline__ uint32_t smem_u32(const void* p) {
    return (uint32_t)__cvta_generic_to_shared(p);
}
__device__ __forceinline__ void cp16(uint32_t dst, const void* src) {
    asm volatile("cp.async.cg.shared.global [%0], [%1], 16;\n" :: "r"(dst), "l"(src));
}
__device__ __forceinline__ void ldm4(uint32_t r[4], uint32_t addr) {
    asm volatile("ldmatrix.sync.aligned.m8n8.x4.shared.b16 {%0,%1,%2,%3}, [%4];"
                 : "=r"(r[0]), "=r"(r[1]), "=r"(r[2]), "=r"(r[3]) : "r"(addr));
}
__device__ __forceinline__ void ldm4t(uint32_t r[4], uint32_t addr) {
    asm volatile("ldmatrix.sync.aligned.m8n8.x4.trans.shared.b16 {%0,%1,%2,%3}, [%4];"
                 : "=r"(r[0]), "=r"(r[1]), "=r"(r[2]), "=r"(r[3]) : "r"(addr));
}
__device__ __forceinline__ void mma16(float c[4], const uint32_t a[4],
                                      uint32_t b0, uint32_t b1) {
    asm volatile(
        "mma.sync.aligned.m16n8k16.row.col.f32.f16.f16.f32 "
        "{%0,%1,%2,%3}, {%4,%5,%6,%7}, {%8,%9}, {%0,%1,%2,%3};"
        : "+f"(c[0]), "+f"(c[1]), "+f"(c[2]), "+f"(c[3])
        : "r"(a[0]), "r"(a[1]), "r"(a[2]), "r"(a[3]), "r"(b0), "r"(b1));
}

#define KPB 528     // 256-half row pitch in bytes (+16B pad)
#define PPB 144     // 64-half row pitch in bytes (+16B pad)

// ---------------------------------------------------------------------------
// Kernel 1: QKV projection, single-term fp16 MMA, 128m x 64n CTA tile.
// ---------------------------------------------------------------------------
#define QSM_XH 0
#define QSM_WH (QSM_XH + 128 * KPB)
#define QSMEM_BYTES (QSM_WH + 64 * KPB)   // 101376

extern __shared__ char smem_raw[];

__global__ __launch_bounds__(256, 1) void qkv_mma_kernel(
    const float* __restrict__ bq, const float* __restrict__ bk,
    const float* __restrict__ bv)
{
    const int tid = threadIdx.x;
    const int w = tid >> 5, lane = tid & 31;
    const int g = lane >> 2, tg = lane & 3;
    const int wm = w & 3, wn = w >> 2;
    const int wsel = blockIdx.x >> 2;
    const int n0   = (blockIdx.x & 3) * 64;
    const int m0   = blockIdx.y * 128;
    const float* bias = (wsel == 0) ? bq : (wsel == 1) ? bk : bv;

    const uint32_t sXH = smem_u32(smem_raw + QSM_XH);
    const uint32_t sWH = smem_u32(smem_raw + QSM_WH);

    {
#pragma unroll
        for (int it = 0; it < 16; it++) {
            int idx = it * 256 + tid, row = idx >> 5, u = idx & 31;
            cp16(sXH + (uint32_t)(row * KPB + u * 16),
                 g_xh + (size_t)(m0 + row) * DIM + u * 8);
        }
        const __half* wh = g_wh + (size_t)wsel * DIM * DIM + (size_t)n0 * DIM;
#pragma unroll
        for (int it = 0; it < 8; it++) {
            int idx = it * 256 + tid, row = idx >> 5, u = idx & 31;
            cp16(sWH + (uint32_t)(row * KPB + u * 16), wh + (size_t)row * DIM + u * 8);
        }
    }
    asm volatile("cp.async.commit_group;\n" ::: "memory");
    asm volatile("cp.async.wait_group 0;\n" ::: "memory");
    __syncthreads();

    const int mm = lane >> 3, rr = lane & 7;
    const uint32_t aX0 = sXH + (32 * wm + ((mm & 1) << 3) + rr) * KPB + (mm >> 1) * 16;
    const uint32_t aX1 = aX0 + 16 * KPB;
    const uint32_t bW  = sWH + (32 * wn + ((mm >> 1) << 3) + rr) * KPB + (mm & 1) * 16;

    float c[2][4][4];
#pragma unroll
    for (int m = 0; m < 2; m++)
#pragma unroll
        for (int n = 0; n < 4; n++)
#pragma unroll
            for (int j = 0; j < 4; j++) c[m][n][j] = 0.f;

#pragma unroll 8
    for (int s = 0; s < 16; s++) {
        uint32_t xa[4], xb[4], b0[4], b1[4];
        ldm4(xa, aX0 + s * 32);
        ldm4(xb, aX1 + s * 32);
        ldm4(b0, bW + s * 32);
        ldm4(b1, bW + 16 * KPB + s * 32);
        mma16(c[0][0], xa, b0[0], b0[1]);
        mma16(c[0][1], xa, b0[2], b0[3]);
        mma16(c[0][2], xa, b1[0], b1[1]);
        mma16(c[0][3], xa, b1[2], b1[3]);
        mma16(c[1][0], xb, b0[0], b0[1]);
        mma16(c[1][1], xb, b0[2], b0[3]);
        mma16(c[1][2], xb, b1[0], b1[1]);
        mma16(c[1][3], xb, b1[2], b1[3]);
    }

    __half* dst = (wsel == 0) ? g_qh : (wsel == 1) ? g_kh : g_vh;
    const int colg = n0 + 32 * wn + 2 * tg;
#pragma unroll
    for (int m = 0; m < 2; m++) {
#pragma unroll
        for (int n = 0; n < 4; n++) {
            int col = colg + 8 * n;
            float b0 = bias[col], b1 = bias[col + 1];
#pragma unroll
            for (int h = 0; h < 2; h++) {
                int row = m0 + 32 * wm + 16 * m + g + 8 * h;
                float y0 = c[m][n][2 * h] + b0, y1 = c[m][n][2 * h + 1] + b1;
                *(half2*)&dst[(size_t)row * DIM + col] =
                    __halves2half2(__float2half_rn(y0), __float2half_rn(y1));
            }
        }
    }
}

// ---------------------------------------------------------------------------
// Kernel 2: flash attention, fp16 m16n8k16, 8 warps — PHASE-PIPELINED:
//   tile t executes [ PV(t) interleaved with S(t+1) ] then softmax(t+1).
//   Two independent ldm->mma streams per warp keep the tensor pipe fed and
//   hide LDSM latency. 1 syncthreads per tile.
//   - Q A-frags register-resident; K,V,P all double-buffered.
//   - cp.async group(t) = { K(t+2), V(t+1) }, waited at end of tile t.
//   S : warp grid 4q x 2k (16q x 32k);  PV: warp grid 2q x 4d (32q x 64d).
// ---------------------------------------------------------------------------
#define TBUF (64 * KPB)                    // 33792 per K/V buffer
#define PBUF (64 * PPB)                    // 9216 per P buffer
#define SM_QH 0
#define SM_KH (SM_QH + TBUF)               // 2 buffers
#define SM_VH (SM_KH + 2 * TBUF)           // 2 buffers
#define SM_PH (SM_VH + 2 * TBUF)           // 2 buffers
#define SM_LS (SM_PH + 2 * PBUF)
#define SMEM_BYTES (SM_LS + 2 * 64 * 4)    // 187904

__global__ __launch_bounds__(256, 1) void attn_mma_kernel(float* __restrict__ out)
{
    const int tid  = threadIdx.x;
    const int w    = tid >> 5;
    const int lane = tid & 31;
    const int g    = lane >> 2;
    const int tg   = lane & 3;
    const int wq   = w & 3;          // S: q strip (16 rows)
    const int wk   = w >> 2;         // S: 32-key strip
    const int pq   = w & 1;          // PV: 32-row q strip
    const int pd   = w >> 1;         // PV: 64-col d strip
    const int bb   = blockIdx.y;
    const int q0   = blockIdx.x * 64;
    const size_t qbase = ((size_t)bb * SEQ + q0) * DIM;

    const uint32_t sQH = smem_u32(smem_raw + SM_QH);
    const uint32_t sKH = smem_u32(smem_raw + SM_KH);
    const uint32_t sVH = smem_u32(smem_raw + SM_VH);
    const uint32_t sPH = smem_u32(smem_raw + SM_PH);
    float* Ls = (float*)(smem_raw + SM_LS);

    const int mm = lane >> 3, rr = lane & 7;
    const uint32_t aQh = sQH + (16 * wq + ((mm & 1) << 3) + rr) * KPB + (mm >> 1) * 16;
    const uint32_t oKh = (uint32_t)((32 * wk + ((mm >> 1) << 3) + rr) * KPB + (mm & 1) * 16);
    const uint32_t oPh = (uint32_t)((32 * pq + ((mm & 1) << 3) + rr) * PPB + (mm >> 1) * 16);
    const uint32_t oV  = (uint32_t)((((mm & 1) << 3) + rr) * KPB + 128 * pd + (mm >> 1) * 16);

    const __half* khg = g_kh + ((size_t)bb * SEQ) * DIM;
    const __half* vhg = g_vh + ((size_t)bb * SEQ) * DIM;

    // ---- prologue: {Q, K0, V0}, then {K1} ----
#pragma unroll
    for (int it = 0; it < 8; it++) {
        int idx = it * 256 + tid, row = idx >> 5, u = idx & 31;
        uint32_t so = (uint32_t)(row * KPB + u * 16);
        size_t   go = (size_t)row * DIM + u * 8;
        cp16(sQH + so, g_qh + qbase + go);
        cp16(sKH + so, khg + go);
        cp16(sVH + so, vhg + go);
    }
    asm volatile("cp.async.commit_group;\n" ::: "memory");
#pragma unroll
    for (int it = 0; it < 8; it++) {
        int idx = it * 256 + tid, row = idx >> 5, u = idx & 31;
        cp16(sKH + TBUF + (uint32_t)(row * KPB + u * 16),
             khg + (size_t)(64 + row) * DIM + u * 8);
    }
    asm volatile("cp.async.commit_group;\n" ::: "memory");
    asm volatile("cp.async.wait_group 0;\n" ::: "memory");
    __syncthreads();

    uint32_t qf[16][4];
#pragma unroll
    for (int s = 0; s < 16; s++) ldm4(qf[s], aQh + s * 32);

    float o2[2][8][4];
#pragma unroll
    for (int m = 0; m < 2; m++)
#pragma unroll
        for (int n = 0; n < 8; n++)
#pragma unroll
            for (int j = 0; j < 4; j++) o2[m][n][j] = 0.f;
    float lr0 = 0.f, lr1 = 0.f;

    const int T = SEQ / 64;
    const float SC = 0.0625f;
    const int rowS = 16 * wq + g;
    const int colS = 32 * wk + 2 * tg;

    // ---- S(0) + softmax(0) -> P buffer 0 ----
    {
        const uint32_t bKh = sKH + oKh;   // K0 in buffer 0
        float sc[4][4];
#pragma unroll
        for (int n = 0; n < 4; n++)
#pragma unroll
            for (int j = 0; j < 4; j++) sc[n][j] = 0.f;
#pragma unroll 8
        for (int s = 0; s < 16; s++) {
            uint32_t ka[4], kb[4];
            ldm4(ka, bKh + s * 32);
            ldm4(kb, bKh + 16 * KPB + s * 32);
            mma16(sc[0], qf[s], ka[0], ka[1]);
            mma16(sc[1], qf[s], ka[2], ka[3]);
            mma16(sc[2], qf[s], kb[0], kb[1]);
            mma16(sc[3], qf[s], kb[2], kb[3]);
        }
        __half* Pw = (__half*)(smem_raw + SM_PH);
#pragma unroll
        for (int n = 0; n < 4; n++) {
            float p0 = __expf(sc[n][0] * SC);
            float p1 = __expf(sc[n][1] * SC);
            float p2 = __expf(sc[n][2] * SC);
            float p3 = __expf(sc[n][3] * SC);
            lr0 += p0 + p1;  lr1 += p2 + p3;
            *(half2*)&Pw[rowS * 72 + colS + 8 * n] =
                __halves2half2(__float2half_rn(p0), __float2half_rn(p1));
            *(half2*)&Pw[(rowS + 8) * 72 + colS + 8 * n] =
                __halves2half2(__float2half_rn(p2), __float2half_rn(p3));
        }
    }
    __syncthreads();

    // ---- main loop: tile t does PV(t) ⊗ S(t+1), softmax(t+1) ----
    for (int tI = 0; tI < T; tI++) {
        // prefetch group(t): K(t+2) -> kbuf[t&1], V(t+1) -> vbuf[(t+1)&1]
        if (tI + 2 < T) {
            const __half* kp = khg + (size_t)(tI + 2) * 64 * DIM;
            uint32_t kb = sKH + (uint32_t)(tI & 1) * TBUF;
#pragma unroll
            for (int it = 0; it < 8; it++) {
                int idx = it * 256 + tid, row = idx >> 5, u = idx & 31;
                cp16(kb + (uint32_t)(row * KPB + u * 16), kp + (size_t)row * DIM + u * 8);
            }
        }
        if (tI + 1 < T) {
            const __half* vp = vhg + (size_t)(tI + 1) * 64 * DIM;
            uint32_t vb = sVH + (uint32_t)((tI + 1) & 1) * TBUF;
#pragma unroll
            for (int it = 0; it < 8; it++) {
                int idx = it * 256 + tid, row = idx >> 5, u = idx & 31;
                cp16(vb + (uint32_t)(row * KPB + u * 16), vp + (size_t)row * DIM + u * 8);
            }
        }
        asm volatile("cp.async.commit_group;\n" ::: "memory");

        const uint32_t aPt = sPH + (uint32_t)(tI & 1) * PBUF + oPh;
        const uint32_t bVt = sVH + (uint32_t)(tI & 1) * TBUF + oV;
        const uint32_t bKn = sKH + (uint32_t)((tI + 1) & 1) * TBUF + oKh;
        const bool doS = (tI + 1 < T);

        float sc[4][4];
#pragma unroll
        for (int n = 0; n < 4; n++)
#pragma unroll
            for (int j = 0; j < 4; j++) sc[n][j] = 0.f;

        // interleaved: 4 chunks, each = PV quarter + 4 S k-steps
#pragma unroll
        for (int s = 0; s < 4; s++) {
            uint32_t pa[2][4];
            ldm4(pa[0], aPt + s * 32);
            ldm4(pa[1], aPt + 16 * PPB + s * 32);
#pragma unroll
            for (int cc = 0; cc < 4; cc++) {
                uint32_t vb[4];
                ldm4t(vb, bVt + (uint32_t)(s * 16 * KPB + cc * 32));
                // S k-step interleaved with this PV block
                if (doS) {
                    const int k = 4 * s + cc;
                    uint32_t ka[4], kb2[4];
                    ldm4(ka, bKn + k * 32);
                    ldm4(kb2, bKn + 16 * KPB + k * 32);
                    mma16(sc[0], qf[k], ka[0], ka[1]);
                    mma16(sc[1], qf[k], ka[2], ka[3]);
                    mma16(sc[2], qf[k], kb2[0], kb2[1]);
                    mma16(sc[3], qf[k], kb2[2], kb2[3]);
                }
                mma16(o2[0][2 * cc],     pa[0], vb[0], vb[1]);
                mma16(o2[0][2 * cc + 1], pa[0], vb[2], vb[3]);
                mma16(o2[1][2 * cc],     pa[1], vb[0], vb[1]);
                mma16(o2[1][2 * cc + 1], pa[1], vb[2], vb[3]);
            }
        }

        // softmax(t+1) -> P buffer (t+1)&1
        if (doS) {
            __half* Pw = (__half*)(smem_raw + SM_PH + ((tI + 1) & 1) * PBUF);
#pragma unroll
            for (int n = 0; n < 4; n++) {
                float p0 = __expf(sc[n][0] * SC);
                float p1 = __expf(sc[n][1] * SC);
                float p2 = __expf(sc[n][2] * SC);
                float p3 = __expf(sc[n][3] * SC);
                lr0 += p0 + p1;  lr1 += p2 + p3;
                *(half2*)&Pw[rowS * 72 + colS + 8 * n] =
                    __halves2half2(__float2half_rn(p0), __float2half_rn(p1));
                *(half2*)&Pw[(rowS + 8) * 72 + colS + 8 * n] =
                    __halves2half2(__float2half_rn(p2), __float2half_rn(p3));
            }
        }

        asm volatile("cp.async.wait_group 0;\n" ::: "memory");
        __syncthreads();
    }

    // ---- epilogue: reduce l once, combine across k-strips, store ----
    lr0 += __shfl_xor_sync(0xffffffffu, lr0, 1);
    lr0 += __shfl_xor_sync(0xffffffffu, lr0, 2);
    lr1 += __shfl_xor_sync(0xffffffffu, lr1, 1);
    lr1 += __shfl_xor_sync(0xffffffffu, lr1, 2);

    if (tg == 0) {
        Ls[wk * 64 + rowS]     = lr0;
        Ls[wk * 64 + rowS + 8] = lr1;
    }
    __syncthreads();

    const int r0 = 32 * pq + g;
    const int r1 = 32 * pq + 16 + g;
    const float i00 = 1.0f / (Ls[r0]     + Ls[64 + r0]);
    const float i01 = 1.0f / (Ls[r0 + 8] + Ls[64 + r0 + 8]);
    const float i10 = 1.0f / (Ls[r1]     + Ls[64 + r1]);
    const float i11 = 1.0f / (Ls[r1 + 8] + Ls[64 + r1 + 8]);

#pragma unroll
    for (int m = 0; m < 2; m++) {
        const float invA = m ? i10 : i00;
        const float invB = m ? i11 : i01;
        const size_t base = ((size_t)bb * SEQ + q0 + 32 * pq + 16 * m + g) * DIM
                          + 64 * pd + 2 * tg;
#pragma unroll
        for (int cc = 0; cc < 8; cc++) {
            float2 vA = make_float2(o2[m][cc][0] * invA, o2[m][cc][1] * invA);
            float2 vB = make_float2(o2[m][cc][2] * invB, o2[m][cc][3] * invB);
            *(float2*)&out[base + 8 * cc]           = vA;
            *(float2*)&out[base + 8 * DIM + 8 * cc] = vB;
        }
    }
}

// ---------------------------------------------------------------------------
extern "C" void kernel_launch(void* const* d_in, const int* in_sizes, int n_in,
                              void* d_out, int out_size)
{
    const float* x  = (const float*)d_in[0];
    const float* Wq = (const float*)d_in[1];
    const float* bq = (const float*)d_in[2];
    const float* Wk = (const float*)d_in[3];
    const float* bk = (const float*)d_in[4];
    const float* Wv = (const float*)d_in[5];
    const float* bv = (const float*)d_in[6];
    float* out = (float*)d_out;

    (void)in_sizes; (void)n_in; (void)out_size;

    split_kernel<<<2048, 256>>>(x, Wq, Wk, Wv);

    cudaFuncSetAttribute(qkv_mma_kernel,
                         cudaFuncAttributeMaxDynamicSharedMemorySize, QSMEM_BYTES);
    qkv_mma_kernel<<<dim3(12, 128), 256, QSMEM_BYTES>>>(bq, bk, bv);

    cudaFuncSetAttribute(attn_mma_kernel,
                         cudaFuncAttributeMaxDynamicSharedMemorySize, SMEM_BYTES);
    attn_mma_kernel<<<dim3(SEQ / 64, BATCH), 256, SMEM_BYTES>>>(out);
}

// round 16
// speedup vs baseline: 1.5943x; 1.0692x over previous
#include <cuda_runtime.h>
#include <cuda_fp16.h>
#include <math.h>
#include <stdint.h>

#define DIM 256
#define BATCH 4
#define SEQ 4096
#define M_TOTAL (BATCH * SEQ)

// fp16 scratch (allocation-free rule: device globals)
__device__ __half g_xh[M_TOTAL * DIM];
__device__ __half g_wh[3 * DIM * DIM];
__device__ __half g_qh[M_TOTAL * DIM];
__device__ __half g_kh[M_TOTAL * DIM];
__device__ __half g_vh[M_TOTAL * DIM];

// ---------------------------------------------------------------------------
// Kernel 0: convert x and W to fp16.
// ---------------------------------------------------------------------------
__global__ __launch_bounds__(256) void split_kernel(
    const float* __restrict__ x,
    const float* __restrict__ Wq, const float* __restrict__ Wk,
    const float* __restrict__ Wv)
{
    const int tid = blockIdx.x * blockDim.x + threadIdx.x;
    const int nt  = gridDim.x * blockDim.x;
    for (int i = tid; i < M_TOTAL * DIM / 4; i += nt) {
        float4 v = ((const float4*)x)[i];
        *(half2*)&g_xh[i * 4]     = __halves2half2(__float2half_rn(v.x), __float2half_rn(v.y));
        *(half2*)&g_xh[i * 4 + 2] = __halves2half2(__float2half_rn(v.z), __float2half_rn(v.w));
    }
    const float* Ws[3] = {Wq, Wk, Wv};
#pragma unroll
    for (int s = 0; s < 3; s++) {
        const float4* wp = (const float4*)Ws[s];
        for (int i = tid; i < DIM * DIM / 4; i += nt) {
            float4 v = wp[i];
            __half* o = g_wh + s * DIM * DIM + i * 4;
            *(half2*)(o)     = __halves2half2(__float2half_rn(v.x), __float2half_rn(v.y));
            *(half2*)(o + 2) = __halves2half2(__float2half_rn(v.z), __float2half_rn(v.w));
        }
    }
}

// ---------------------------------------------------------------------------
// Warp-MMA helpers (plain PTX — valid on compute_103)
// ---------------------------------------------------------------------------
__device__ __forceinline__ uint32_t smem_u32(const void* p) {
    return (uint32_t)__cvta_generic_to_shared(p);
}
__device__ __forceinline__ void cp16(uint32_t dst, const void* src) {
    asm volatile("cp.async.cg.shared.global [%0], [%1], 16;\n" :: "r"(dst), "l"(src));
}
__device__ __forceinline__ void ldm4(uint32_t r[4], uint32_t addr) {
    asm volatile("ldmatrix.sync.aligned.m8n8.x4.shared.b16 {%0,%1,%2,%3}, [%4];"
                 : "=r"(r[0]), "=r"(r[1]), "=r"(r[2]), "=r"(r[3]) : "r"(addr));
}
__device__ __forceinline__ void ldm4t(uint32_t r[4], uint32_t addr) {
    asm volatile("ldmatrix.sync.aligned.m8n8.x4.trans.shared.b16 {%0,%1,%2,%3}, [%4];"
                 : "=r"(r[0]), "=r"(r[1]), "=r"(r[2]), "=r"(r[3]) : "r"(addr));
}
__device__ __forceinline__ void mma16(float c[4], const uint32_t a[4],
                                      uint32_t b0, uint32_t b1) {
    asm volatile(
        "mma.sync.aligned.m16n8k16.row.col.f32.f16.f16.f32 "
        "{%0,%1,%2,%3}, {%4,%5,%6,%7}, {%8,%9}, {%0,%1,%2,%3};"
        : "+f"(c[0]), "+f"(c[1]), "+f"(c[2]), "+f"(c[3])
        : "r"(a[0]), "r"(a[1]), "r"(a[2]), "r"(a[3]), "r"(b0), "r"(b1));
}

#define KPB 528     // 256-half row pitch in bytes (+16B pad)
#define PPB 144     // 64-half row pitch in bytes (+16B pad)

// ---------------------------------------------------------------------------
// Kernel 1: QKV projection, single-term fp16 MMA, 128m x 64n CTA tile.
// ---------------------------------------------------------------------------
#define QSM_XH 0
#define QSM_WH (QSM_XH + 128 * KPB)
#define QSMEM_BYTES (QSM_WH + 64 * KPB)   // 101376

extern __shared__ char smem_raw[];

__global__ __launch_bounds__(256, 1) void qkv_mma_kernel(
    const float* __restrict__ bq, const float* __restrict__ bk,
    const float* __restrict__ bv)
{
    const int tid = threadIdx.x;
    const int w = tid >> 5, lane = tid & 31;
    const int g = lane >> 2, tg = lane & 3;
    const int wm = w & 3, wn = w >> 2;
    const int wsel = blockIdx.x >> 2;
    const int n0   = (blockIdx.x & 3) * 64;
    const int m0   = blockIdx.y * 128;
    const float* bias = (wsel == 0) ? bq : (wsel == 1) ? bk : bv;

    const uint32_t sXH = smem_u32(smem_raw + QSM_XH);
    const uint32_t sWH = smem_u32(smem_raw + QSM_WH);

    {
#pragma unroll
        for (int it = 0; it < 16; it++) {
            int idx = it * 256 + tid, row = idx >> 5, u = idx & 31;
            cp16(sXH + (uint32_t)(row * KPB + u * 16),
                 g_xh + (size_t)(m0 + row) * DIM + u * 8);
        }
        const __half* wh = g_wh + (size_t)wsel * DIM * DIM + (size_t)n0 * DIM;
#pragma unroll
        for (int it = 0; it < 8; it++) {
            int idx = it * 256 + tid, row = idx >> 5, u = idx & 31;
            cp16(sWH + (uint32_t)(row * KPB + u * 16), wh + (size_t)row * DIM + u * 8);
        }
    }
    asm volatile("cp.async.commit_group;\n" ::: "memory");
    asm volatile("cp.async.wait_group 0;\n" ::: "memory");
    __syncthreads();

    const int mm = lane >> 3, rr = lane & 7;
    const uint32_t aX0 = sXH + (32 * wm + ((mm & 1) << 3) + rr) * KPB + (mm >> 1) * 16;
    const uint32_t aX1 = aX0 + 16 * KPB;
    const uint32_t bW  = sWH + (32 * wn + ((mm >> 1) << 3) + rr) * KPB + (mm & 1) * 16;

    float c[2][4][4];
#pragma unroll
    for (int m = 0; m < 2; m++)
#pragma unroll
        for (int n = 0; n < 4; n++)
#pragma unroll
            for (int j = 0; j < 4; j++) c[m][n][j] = 0.f;

#pragma unroll 8
    for (int s = 0; s < 16; s++) {
        uint32_t xa[4], xb[4], b0[4], b1[4];
        ldm4(xa, aX0 + s * 32);
        ldm4(xb, aX1 + s * 32);
        ldm4(b0, bW + s * 32);
        ldm4(b1, bW + 16 * KPB + s * 32);
        mma16(c[0][0], xa, b0[0], b0[1]);
        mma16(c[0][1], xa, b0[2], b0[3]);
        mma16(c[0][2], xa, b1[0], b1[1]);
        mma16(c[0][3], xa, b1[2], b1[3]);
        mma16(c[1][0], xb, b0[0], b0[1]);
        mma16(c[1][1], xb, b0[2], b0[3]);
        mma16(c[1][2], xb, b1[0], b1[1]);
        mma16(c[1][3], xb, b1[2], b1[3]);
    }

    __half* dst = (wsel == 0) ? g_qh : (wsel == 1) ? g_kh : g_vh;
    const int colg = n0 + 32 * wn + 2 * tg;
#pragma unroll
    for (int m = 0; m < 2; m++) {
#pragma unroll
        for (int n = 0; n < 4; n++) {
            int col = colg + 8 * n;
            float b0 = bias[col], b1 = bias[col + 1];
#pragma unroll
            for (int h = 0; h < 2; h++) {
                int row = m0 + 32 * wm + 16 * m + g + 8 * h;
                float y0 = c[m][n][2 * h] + b0, y1 = c[m][n][2 * h + 1] + b1;
                *(half2*)&dst[(size_t)row * DIM + col] =
                    __halves2half2(__float2half_rn(y0), __float2half_rn(y1));
            }
        }
    }
}

// ---------------------------------------------------------------------------
// Kernel 2: flash attention, fp16 m16n8k16 — 128 threads, 2 CTAs/SM.
// CTA = (batch, 64 queries), 4 warps, 64-key tiles:
//   S : warp w owns q rows 16w..16w+15 across ALL 64 keys (sc[8][4]).
//   PV: warp w owns d cols 64w..64w+63 across ALL 64 q (o[4][8][4], 128 regs).
// smem 110,848 B -> two CTAs co-resident per SM: one CTA's LDSM phase
// overlaps the other's HMMA phase (single-CTA phases were serialized).
// 256 CTAs / 2-per-SM = single wave.
// K/V/P single-buffered; R10-proven prefetch (unconditional commits, wait 1).
// ---------------------------------------------------------------------------
#define SM_QH 0
#define SM_KH (SM_QH + 64 * KPB)          // 33792
#define SM_VH (SM_KH + 64 * KPB)          // 67584
#define SM_PH (SM_VH + 64 * KPB)          // 101376
#define SM_LS (SM_PH + 64 * PPB)          // 110592
#define SMEM_BYTES (SM_LS + 64 * 4)       // 110848

__global__ __launch_bounds__(128, 2) void attn_mma_kernel(float* __restrict__ out)
{
    const int tid  = threadIdx.x;
    const int w    = tid >> 5;       // warp 0..3
    const int lane = tid & 31;
    const int g    = lane >> 2;
    const int tg   = lane & 3;
    const int bb   = blockIdx.y;
    const int q0   = blockIdx.x * 64;
    const size_t qbase = ((size_t)bb * SEQ + q0) * DIM;

    const uint32_t sQH = smem_u32(smem_raw + SM_QH);
    const uint32_t sKH = smem_u32(smem_raw + SM_KH);
    const uint32_t sVH = smem_u32(smem_raw + SM_VH);
    const uint32_t sPH = smem_u32(smem_raw + SM_PH);
    __half* PhS = (__half*)(smem_raw + SM_PH);
    float*  Ls  = (float*)(smem_raw + SM_LS);

    const int mm = lane >> 3, rr = lane & 7;
    // S: A = Q rows 16w.., fixed per warp
    const uint32_t aQ = sQH + (16 * w + ((mm & 1) << 3) + rr) * KPB + (mm >> 1) * 16;
    // S: B = K, block c (16 keys) at +16c*KPB
    const uint32_t bK = sKH + (((mm >> 1) << 3) + rr) * KPB + (mm & 1) * 16;
    // PV: A = P, m-strip at +16m*PPB
    const uint32_t aP = sPH + (((mm & 1) << 3) + rr) * PPB + (mm >> 1) * 16;
    // PV: B = V (trans), d strip 64w (128 bytes), k-step s at +16s*KPB
    const uint32_t bV = sVH + (((mm & 1) << 3) + rr) * KPB + (uint32_t)w * 128 + (mm >> 1) * 16;

    const __half* khg = g_kh + ((size_t)bb * SEQ) * DIM;
    const __half* vhg = g_vh + ((size_t)bb * SEQ) * DIM;

    // ---- prologue: {Q, K0} group, {V0} group ----
#pragma unroll
    for (int it = 0; it < 16; it++) {
        int idx = it * 128 + tid, row = idx >> 5, u = idx & 31;
        uint32_t so = (uint32_t)(row * KPB + u * 16);
        size_t   go = (size_t)row * DIM + u * 8;
        cp16(sQH + so, g_qh + qbase + go);
        cp16(sKH + so, khg + go);
    }
    asm volatile("cp.async.commit_group;\n" ::: "memory");
#pragma unroll
    for (int it = 0; it < 16; it++) {
        int idx = it * 128 + tid, row = idx >> 5, u = idx & 31;
        cp16(sVH + (uint32_t)(row * KPB + u * 16), vhg + (size_t)row * DIM + u * 8);
    }
    asm volatile("cp.async.commit_group;\n" ::: "memory");

    float o[4][8][4];
#pragma unroll
    for (int m = 0; m < 4; m++)
#pragma unroll
        for (int n = 0; n < 8; n++)
#pragma unroll
            for (int j = 0; j < 4; j++) o[m][n][j] = 0.f;
    float lr0 = 0.f, lr1 = 0.f;

    const int T = SEQ / 64;
    const float SC = 0.0625f;
    const int rowS = 16 * w + g;

    for (int tI = 0; tI < T; tI++) {
        asm volatile("cp.async.wait_group 1;\n" ::: "memory");  // K(tI) ready
        __syncthreads();

        // ---- S = Q @ K^T : warp tile 16q x 64k ----
        float sc[8][4];
#pragma unroll
        for (int n = 0; n < 8; n++)
#pragma unroll
            for (int j = 0; j < 4; j++) sc[n][j] = 0.f;

#pragma unroll 4
        for (int s = 0; s < 16; s++) {
            uint32_t qh[4];
            ldm4(qh, aQ + s * 32);
#pragma unroll
            for (int c = 0; c < 4; c++) {
                uint32_t kb[4];
                ldm4(kb, bK + (uint32_t)(c * 16 * KPB) + s * 32);
                mma16(sc[2 * c],     qh, kb[0], kb[1]);
                mma16(sc[2 * c + 1], qh, kb[2], kb[3]);
            }
        }

        // ---- softmax: p = exp(s/16); P -> smem; defer row sums ----
#pragma unroll
        for (int n = 0; n < 8; n++) {
            float p0 = __expf(sc[n][0] * SC);
            float p1 = __expf(sc[n][1] * SC);
            float p2 = __expf(sc[n][2] * SC);
            float p3 = __expf(sc[n][3] * SC);
            lr0 += p0 + p1;  lr1 += p2 + p3;
            *(half2*)&PhS[rowS * 72 + 2 * tg + 8 * n] =
                __halves2half2(__float2half_rn(p0), __float2half_rn(p1));
            *(half2*)&PhS[(rowS + 8) * 72 + 2 * tg + 8 * n] =
                __halves2half2(__float2half_rn(p2), __float2half_rn(p3));
        }
        __syncthreads();   // P visible; K reads done

        // ---- prefetch K(tI+1) (overlaps PV) ----
        if (tI + 1 < T) {
            const __half* kp = khg + (size_t)(tI + 1) * 64 * DIM;
#pragma unroll
            for (int it = 0; it < 16; it++) {
                int idx = it * 128 + tid, row = idx >> 5, u = idx & 31;
                cp16(sKH + (uint32_t)(row * KPB + u * 16), kp + (size_t)row * DIM + u * 8);
            }
        }
        asm volatile("cp.async.commit_group;\n" ::: "memory");

        asm volatile("cp.async.wait_group 1;\n" ::: "memory");  // V(tI) ready
        __syncthreads();

        // ---- PV: O += P @ V ; warp tile 64q x 64d ----
#pragma unroll
        for (int s = 0; s < 4; s++) {
            uint32_t pa[4][4];
#pragma unroll
            for (int m = 0; m < 4; m++)
                ldm4(pa[m], aP + (uint32_t)(m * 16 * PPB) + s * 32);
#pragma unroll
            for (int cc = 0; cc < 4; cc++) {
                uint32_t vb[4];
                ldm4t(vb, bV + (uint32_t)(s * 16 * KPB) + cc * 32);
#pragma unroll
                for (int m = 0; m < 4; m++) {
                    mma16(o[m][2 * cc],     pa[m], vb[0], vb[1]);
                    mma16(o[m][2 * cc + 1], pa[m], vb[2], vb[3]);
                }
            }
        }
        __syncthreads();   // V, P reads done

        // ---- prefetch V(tI+1) (overlaps next S) ----
        if (tI + 1 < T) {
            const __half* vp = vhg + (size_t)(tI + 1) * 64 * DIM;
#pragma unroll
            for (int it = 0; it < 16; it++) {
                int idx = it * 128 + tid, row = idx >> 5, u = idx & 31;
                cp16(sVH + (uint32_t)(row * KPB + u * 16), vp + (size_t)row * DIM + u * 8);
            }
        }
        asm volatile("cp.async.commit_group;\n" ::: "memory");
    }

    // ---- epilogue: l complete per warp (full key range) ----
    lr0 += __shfl_xor_sync(0xffffffffu, lr0, 1);
    lr0 += __shfl_xor_sync(0xffffffffu, lr0, 2);
    lr1 += __shfl_xor_sync(0xffffffffu, lr1, 1);
    lr1 += __shfl_xor_sync(0xffffffffu, lr1, 2);
    if (tg == 0) {
        Ls[rowS]     = lr0;
        Ls[rowS + 8] = lr1;
    }
    __syncthreads();

#pragma unroll
    for (int m = 0; m < 4; m++) {
        const float invA = 1.0f / Ls[16 * m + g];
        const float invB = 1.0f / Ls[16 * m + 8 + g];
        const size_t base = ((size_t)bb * SEQ + q0 + 16 * m + g) * DIM + 64 * w + 2 * tg;
#pragma unroll
        for (int n = 0; n < 8; n++) {
            float2 vA = make_float2(o[m][n][0] * invA, o[m][n][1] * invA);
            float2 vB = make_float2(o[m][n][2] * invB, o[m][n][3] * invB);
            *(float2*)&out[base + 8 * n]           = vA;
            *(float2*)&out[base + 8 * DIM + 8 * n] = vB;
        }
    }
}

// ---------------------------------------------------------------------------
extern "C" void kernel_launch(void* const* d_in, const int* in_sizes, int n_in,
                              void* d_out, int out_size)
{
    const float* x  = (const float*)d_in[0];
    const float* Wq = (const float*)d_in[1];
    const float* bq = (const float*)d_in[2];
    const float* Wk = (const float*)d_in[3];
    const float* bk = (const float*)d_in[4];
    const float* Wv = (const float*)d_in[5];
    const float* bv = (const float*)d_in[6];
    float* out = (float*)d_out;

    (void)in_sizes; (void)n_in; (void)out_size;

    split_kernel<<<2048, 256>>>(x, Wq, Wk, Wv);

    cudaFuncSetAttribute(qkv_mma_kernel,
                         cudaFuncAttributeMaxDynamicSharedMemorySize, QSMEM_BYTES);
    qkv_mma_kernel<<<dim3(12, 128), 256, QSMEM_BYTES>>>(bq, bk, bv);

    cudaFuncSetAttribute(attn_mma_kernel,
                         cudaFuncAttributeMaxDynamicSharedMemorySize, SMEM_BYTES);
    attn_mma_kernel<<<dim3(SEQ / 64, BATCH), 128, SMEM_BYTES>>>(out);
}